// round 12
// baseline (speedup 1.0000x reference)
#include <cuda_runtime.h>
#include <cuda_fp16.h>
#include <math.h>
#include <stdint.h>

// ---------------------------------------------------------------------------
// Problem dims
// ---------------------------------------------------------------------------
#define NB      8
#define LQ      512
#define LKV     16384
#define CH_LAT  1024
#define CH_IN   768
#define DH      128
#define NH      8
#define BH      (NB*NH)        // 64
#define MKV     (NB*LKV)       // 131072
#define MQ      (NB*LQ)        // 4096

// 1/sqrt(128) * log2(e)  (folded into Q; softmax uses exp2)
#define QSCALE  (0.08838834764831845f * 1.4426950408889634f)

// ---------------------------------------------------------------------------
// Scratch (device globals; uint4-typed for 16B alignment, cast to __half)
// ---------------------------------------------------------------------------
__device__ float g_mu_kv[MKV], g_rs_kv[MKV];
__device__ float g_mu_q[MQ],   g_rs_q[MQ];
__device__ uint4 g_Xkv4[(size_t)MKV*CH_IN/8];    // half copy of input_kv
__device__ uint4 g_Xq4 [(size_t)MQ*CH_LAT/8];    // half copy of latent
__device__ uint4 g_Qb4 [(size_t)BH*LQ*DH/8];     // half [bh][q][d], QSCALE folded
__device__ uint4 g_Kb4 [(size_t)BH*LKV*DH/8];    // half [bh][l][d]
__device__ uint4 g_Vt4 [(size_t)BH*DH*LKV/8];    // half [bh][d][l]
__device__ uint4 g_AO4 [(size_t)MQ*1024/8];      // half [b*512+q][h*128+d]
__device__ uint4 g_WTkv4[2048*768/8];            // half (gamma*W)^T; <1024: K, >=1024: V
__device__ uint4 g_WTq4 [1024*1024/8];
__device__ uint4 g_WTo4 [1024*1024/8];
__device__ float g_vb[2048], g_vg[2048];         // beta^T W, gamma^T W (KV)
__device__ float g_vbq[1024], g_vgq[1024];       // (Q)
__device__ float g_vbp[8*2048], g_vgp[8*2048];   // split-K partials

// ---------------------------------------------------------------------------
// helpers
// ---------------------------------------------------------------------------
__device__ __forceinline__ float ex2(float x) {
    float y; asm("ex2.approx.ftz.f32 %0, %1;" : "=f"(y) : "f"(x)); return y;
}
__device__ __forceinline__ unsigned pack2h(float a, float b) {
    __half2 h = __floats2half2_rn(a, b);
    return *(unsigned*)&h;
}
__device__ __forceinline__ uint32_t smem_u32(const void* p) {
    uint32_t a;
    asm("{ .reg .u64 t; cvta.to.shared.u64 t, %1; cvt.u32.u64 %0, t; }" : "=r"(a) : "l"(p));
    return a;
}
__device__ __forceinline__ void cpa16(uint32_t dst, const void* src) {
    asm volatile("cp.async.cg.shared.global [%0], [%1], 16;" :: "r"(dst), "l"(src));
}
#define CP_COMMIT() asm volatile("cp.async.commit_group;")
#define CP_WAIT(N)  asm volatile("cp.async.wait_group %0;" :: "n"(N))

__device__ __forceinline__ void mma_f16(float* c, const unsigned* a, const unsigned* b) {
    asm volatile(
        "mma.sync.aligned.m16n8k16.row.col.f32.f16.f16.f32 "
        "{%0,%1,%2,%3}, {%4,%5,%6,%7}, {%8,%9}, {%0,%1,%2,%3};\n"
        : "+f"(c[0]), "+f"(c[1]), "+f"(c[2]), "+f"(c[3])
        : "r"(a[0]), "r"(a[1]), "r"(a[2]), "r"(a[3]), "r"(b[0]), "r"(b[1]));
}
__device__ __forceinline__ void ldsm4(unsigned* r, uint32_t a) {
    asm volatile("ldmatrix.sync.aligned.m8n8.x4.shared.b16 {%0,%1,%2,%3}, [%4];"
                 : "=r"(r[0]), "=r"(r[1]), "=r"(r[2]), "=r"(r[3]) : "r"(a));
}

// Swizzled word (b32 = half2) offsets
__device__ __forceinline__ int swQ64(int row, int w) {   // 64-word (128-half) rows
    return row * 64 + ((((w >> 2) ^ row) & 15) << 2) + (w & 3);
}

// ---------------------------------------------------------------------------
// Row stats + half copy (one warp per row)
// ---------------------------------------------------------------------------
__global__ void rowstats_kernel(const float* __restrict__ X, __half* __restrict__ Xh,
                                float* __restrict__ mu, float* __restrict__ rs, int cols)
{
    int row  = blockIdx.x * 8 + (threadIdx.x >> 5);
    int lane = threadIdx.x & 31;
    const float* xr = X + (size_t)row * cols;
    __half* xo = Xh + (size_t)row * cols;
    float s = 0.f, s2 = 0.f;
    for (int c = lane; c < cols; c += 32) {
        float v = xr[c];
        xo[c] = __float2half_rn(v);
        s += v; s2 += v * v;
    }
#pragma unroll
    for (int o = 16; o; o >>= 1) {
        s  += __shfl_xor_sync(0xffffffffu, s,  o);
        s2 += __shfl_xor_sync(0xffffffffu, s2, o);
    }
    if (lane == 0) {
        float m = s / cols;
        float var = fmaxf(s2 / cols - m * m, 0.f);
        mu[row] = m; rs[row] = rsqrtf(var + 1e-5f);
    }
}

// ---------------------------------------------------------------------------
// Weight transpose: out[c][r] = half(in[r][c] * (scale?scale[r]:1))
// ---------------------------------------------------------------------------
__global__ void wtrans_kernel(const float* __restrict__ in, __half* __restrict__ out,
                              int R, int C, const float* __restrict__ scale)
{
    __shared__ float t[32][33];
    int c0 = blockIdx.x * 32, r0 = blockIdx.y * 32;
    int tx = threadIdx.x, ty = threadIdx.y;
#pragma unroll
    for (int j = 0; j < 4; j++) {
        int r = r0 + ty + j * 8;
        float v = in[(size_t)r * C + c0 + tx];
        if (scale) v *= scale[r];
        t[ty + j * 8][tx] = v;
    }
    __syncthreads();
#pragma unroll
    for (int j = 0; j < 4; j++)
        out[(size_t)(c0 + ty + j * 8) * R + r0 + tx] = __float2half_rn(t[tx][ty + j * 8]);
}

// ---------------------------------------------------------------------------
// vb/vg fold vectors: split-K partials + reduce.
// Partial: block = 64 cols x 128-row slice (blockIdx.y). n<1024 -> W0 else W1.
// ---------------------------------------------------------------------------
__global__ void vbvg_part(const float* __restrict__ W0, const float* __restrict__ W1,
                          const float* __restrict__ gamma, const float* __restrict__ beta,
                          float* __restrict__ vbp, float* __restrict__ vgp, int N)
{
    __shared__ float sbv[4][64], sgv[4][64];
    int nl = threadIdx.x & 63;
    int n = blockIdx.x * 64 + nl;
    int rg = threadIdx.x >> 6;
    int r0 = blockIdx.y * 128;
    const float* W = (n < 1024) ? W0 : W1;
    int nn = n & 1023;
    float sb = 0.f, sg = 0.f;
#pragma unroll 4
    for (int r = r0 + rg; r < r0 + 128; r += 4) {
        float w = W[(size_t)r * 1024 + nn];
        sb += beta[r] * w;
        sg += gamma[r] * w;
    }
    sbv[rg][nl] = sb;
    sgv[rg][nl] = sg;
    __syncthreads();
    if (threadIdx.x < 64) {
        vbp[(size_t)blockIdx.y * N + n] = sbv[0][nl] + sbv[1][nl] + sbv[2][nl] + sbv[3][nl];
        vgp[(size_t)blockIdx.y * N + n] = sgv[0][nl] + sgv[1][nl] + sgv[2][nl] + sgv[3][nl];
    }
}

__global__ void vbvg_reduce(const float* __restrict__ vbp, const float* __restrict__ vgp,
                            float* __restrict__ vb, float* __restrict__ vg, int S, int N)
{
    int n = blockIdx.x * 256 + threadIdx.x;
    float a = 0.f, b = 0.f;
    for (int s = 0; s < S; s++) { a += vbp[(size_t)s * N + n]; b += vgp[(size_t)s * N + n]; }
    vb[n] = a; vg[n] = b;
}

// ---------------------------------------------------------------------------
// FP16 GEMM: block 128x256, BK=32, 256 threads (8 warps 2x4), warp 64x64,
// m16n8k16, cp.async 4-stage, ldmatrix fragment loads.
// MODE 0: -> g_Kb half (n<1024) / g_Vt half transposed (n>=1024)
// MODE 1: -> g_Qb half, *QSCALE
// MODE 2: -> float row-major C
// ---------------------------------------------------------------------------
#define G_STAGE 24576
#define G_SMEM  (4*G_STAGE)      // 96KB

template<int MODE>
__global__ __launch_bounds__(256, 1)
void gemm_h(const __half* __restrict__ A, const __half* __restrict__ WT,
            const float* __restrict__ mu, const float* __restrict__ rs,
            const float* __restrict__ vb, const float* __restrict__ vg,
            float* __restrict__ C, int K, int moff)
{
    extern __shared__ char sm[];
    const uint32_t sb = smem_u32(sm);
    const int tid = threadIdx.x;
    const int lane = tid & 31, wid = tid >> 5;
    const int wm = wid >> 2, wn = wid & 3;
    const int g = lane >> 2, t = lane & 3;
    const int m0 = (blockIdx.y + moff) * 128, n0 = blockIdx.x * 256;
    const int KC = K >> 5;

    const __half* Ag = A  + (size_t)m0 * K;
    const __half* Bg = WT + (size_t)n0 * K;

    const __half* a_src[2]; uint32_t a_dst[2];
#pragma unroll
    for (int it = 0; it < 2; it++) {
        int idx = tid + it * 256, row = idx >> 2, blk = idx & 3;
        a_src[it] = Ag + (size_t)row * K + blk * 8;
        a_dst[it] = (row * 16 + ((((blk ^ (row >> 1)) & 3)) << 2)) * 4;
    }
    const __half* b_src[4]; uint32_t b_dst[4];
#pragma unroll
    for (int it = 0; it < 4; it++) {
        int idx = tid + it * 256, row = idx >> 2, blk = idx & 3;
        b_src[it] = Bg + (size_t)row * K + blk * 8;
        b_dst[it] = 8192 + (row * 16 + ((((blk ^ (row >> 1)) & 3)) << 2)) * 4;
    }

    // ldmatrix per-lane geometry
    const int a_row = ((lane >> 3) & 1) * 8 + (lane & 7);
    const int a_ch  = lane >> 4;
    const uint32_t a_ro = (uint32_t)(wm * 64 + a_row) * 64;
    const int a_x   = (a_row >> 1) & 3;
    const int b_row = ((lane >> 4) & 1) * 8 + (lane & 7);
    const int b_ch  = (lane >> 3) & 1;
    const uint32_t b_ro = (uint32_t)(wn * 64 + b_row) * 64;
    const int b_x   = (b_row >> 1) & 3;

    float acc[4][8][4];
#pragma unroll
    for (int i = 0; i < 4; i++)
#pragma unroll
        for (int j = 0; j < 8; j++)
#pragma unroll
            for (int r = 0; r < 4; r++) acc[i][j][r] = 0.f;

#pragma unroll
    for (int s = 0; s < 3; s++) {
        uint32_t base = sb + s * G_STAGE;
        int k0 = s * 32;
#pragma unroll
        for (int it = 0; it < 2; it++) cpa16(base + a_dst[it], a_src[it] + k0);
#pragma unroll
        for (int it = 0; it < 4; it++) cpa16(base + b_dst[it], b_src[it] + k0);
        CP_COMMIT();
    }

    for (int c = 0; c < KC; c++) {
        CP_WAIT(2);
        __syncthreads();
        if (c + 3 < KC) {
            uint32_t base = sb + ((c + 3) & 3) * G_STAGE;
            int k0 = (c + 3) * 32;
#pragma unroll
            for (int it = 0; it < 2; it++) cpa16(base + a_dst[it], a_src[it] + k0);
#pragma unroll
            for (int it = 0; it < 4; it++) cpa16(base + b_dst[it], b_src[it] + k0);
        }
        CP_COMMIT();

        const uint32_t abase = sb + (c & 3) * G_STAGE;
        const uint32_t bbase = abase + 8192;
#pragma unroll
        for (int ks = 0; ks < 2; ks++) {
            unsigned afr[4][4], bfr[8][2];
            uint32_t aoff = abase + a_ro + ((((ks * 2 + a_ch) ^ a_x) & 3) << 4);
#pragma unroll
            for (int i = 0; i < 4; i++) ldsm4(afr[i], aoff + i * 1024);
            uint32_t boff = bbase + b_ro + ((((ks * 2 + b_ch) ^ b_x) & 3) << 4);
#pragma unroll
            for (int jp = 0; jp < 4; jp++) {
                unsigned tmp[4];
                ldsm4(tmp, boff + jp * 1024);
                bfr[2*jp][0] = tmp[0]; bfr[2*jp][1] = tmp[1];
                bfr[2*jp+1][0] = tmp[2]; bfr[2*jp+1][1] = tmp[3];
            }
#pragma unroll
            for (int i = 0; i < 4; i++)
#pragma unroll
                for (int j = 0; j < 8; j++)
                    mma_f16(acc[i][j], afr[i], bfr[j]);
        }
    }
    CP_WAIT(0);
    __syncthreads();

    // ---- epilogue
    float Rr[8], MR[8];
    if (MODE != 2) {
#pragma unroll
        for (int i = 0; i < 4; i++)
#pragma unroll
            for (int half = 0; half < 2; half++) {
                int r = m0 + wm * 64 + i * 16 + g + half * 8;
                float rv = rs[r];
                Rr[i * 2 + half] = rv;
                MR[i * 2 + half] = mu[r] * rv;
            }
    }
    float vbv[16], vgv[16];
    if (MODE != 2) {
#pragma unroll
        for (int j = 0; j < 8; j++) {
            int cg = n0 + wn * 64 + j * 8 + 2 * t;
            vbv[2*j] = vb[cg]; vbv[2*j+1] = vb[cg+1];
            vgv[2*j] = vg[cg]; vgv[2*j+1] = vg[cg+1];
        }
    }

    const bool vpart = (MODE == 0) && (n0 >= 1024);
    __half* st = (__half*)sm;
    __half* Kb = (__half*)g_Kb4;
    __half* Qb = (__half*)g_Qb4;
    __half* Vt = (__half*)g_Vt4;

#pragma unroll
    for (int i = 0; i < 4; i++) {
#pragma unroll
        for (int j = 0; j < 8; j++) {
#pragma unroll
            for (int half = 0; half < 2; half++) {
                int rl = wm * 64 + i * 16 + g + half * 8;
                int r = m0 + rl;
                int cl = wn * 64 + j * 8 + 2 * t;
                int cg = n0 + cl;
                float v0 = acc[i][j][half * 2 + 0];
                float v1 = acc[i][j][half * 2 + 1];
                if (MODE != 2) {
                    float R = Rr[i * 2 + half], M = MR[i * 2 + half];
                    v0 = R * v0 + vbv[2*j]   - M * vgv[2*j];
                    v1 = R * v1 + vbv[2*j+1] - M * vgv[2*j+1];
                }
                if (MODE == 0) {
                    if (!vpart) {
                        int h = cg >> 7, d = cg & 127;
                        int bb2 = r >> 14, l = r & 16383;
                        unsigned u = pack2h(v0, v1);
                        *(unsigned*)(Kb + ((((size_t)(bb2 * 8 + h)) << 14) + l) * 128 + d) = u;
                    } else {
                        st[cl * 136 + rl]       = __float2half_rn(v0);
                        st[(cl + 1) * 136 + rl] = __float2half_rn(v1);
                    }
                } else if (MODE == 1) {
                    int h = cg >> 7, d = cg & 127;
                    int bb2 = r >> 9, q = r & 511;
                    unsigned u = pack2h(QSCALE * v0, QSCALE * v1);
                    *(unsigned*)(Qb + (((size_t)(bb2 * 8 + h)) * 512 + q) * 128 + d) = u;
                } else {
                    *(float2*)(C + (size_t)r * 1024 + cg) = make_float2(v0, v1);
                }
            }
        }
    }
    if (vpart) {
        __syncthreads();
        int bb2 = m0 >> 14, l0 = m0 & 16383;
#pragma unroll
        for (int cl2 = 0; cl2 < 32; cl2++) {
            int c = wid * 32 + cl2;
            int cg = n0 + c - 1024;
            int h = cg >> 7, d = cg & 127;
            uint2 v = *(const uint2*)&st[c * 136 + lane * 4];
            *(uint2*)(Vt + ((size_t)(bb2 * 8 + h) * 128 + d) * LKV + l0 + lane * 4) = v;
        }
    }
}

// ---------------------------------------------------------------------------
// FP16 flash attention. Br=128, Bc=128, 256 threads, m16n8k16, cp.async
// 2-stage, ldmatrix loads, Q fragments hoisted to registers (loop-invariant).
//   S:  warps 4x2 (q32 x l64);  PV: warps 2x4 (q64 x d32).
// Smem: Q 32KB | stage0 K32+V32 | stage1 K32+V32 | P 32KB (ls overlays P).
// ---------------------------------------------------------------------------
#define AT_Q     0
#define AT_STG   32768
#define AT_P     163840
#define A_SMEM_BYTES 196608

__global__ __launch_bounds__(256, 1)
void attn_h(const __half* __restrict__ Qb, const __half* __restrict__ Kb,
            const __half* __restrict__ Vt, __half* __restrict__ AO)
{
    extern __shared__ char sm[];
    const uint32_t sb = smem_u32(sm);
    const int tid = threadIdx.x;
    const int lane = tid & 31, wid = tid >> 5;
    const int g = lane >> 2, t = lane & 3;
    const int bh = blockIdx.y;
    const int q0 = blockIdx.x * 128;

    const int wq4 = wid & 3, wl = wid >> 2;   // S phase: q 32, l 64
    const int wq2 = wid & 1, wd = wid >> 1;   // PV phase: q 64, d 32

    const __half* Qg = Qb + ((size_t)bh * LQ + q0) * DH;
    const __half* Kg = Kb + (size_t)bh * LKV * DH;
    const __half* Vg = Vt + (size_t)bh * DH * LKV;

    unsigned* Ps = (unsigned*)(sm + AT_P);

    // ldmatrix per-lane geometry
    const int ar = ((lane >> 3) & 1) * 8 + (lane & 7);
    const int ach = lane >> 4;
    const int br = ((lane >> 4) & 1) * 8 + (lane & 7);
    const int bch = (lane >> 3) & 1;
    const uint32_t q_ro = sb + AT_Q + (uint32_t)(wq4 * 32 + ar) * 256;
    const uint32_t p_ro = sb + AT_P + (uint32_t)(wq2 * 64 + ar) * 256;

    // staging assignments
    const __half* k_src[8]; uint32_t k_dst[8];
    const __half* v_src[8]; uint32_t v_dst[8];
#pragma unroll
    for (int it = 0; it < 8; it++) {
        int idx = tid + it * 256, row = idx >> 4, blk = idx & 15;
        uint32_t sw = (row * 64 + (((blk ^ row) & 15) << 2)) * 4;
        k_src[it] = Kg + (size_t)row * 128 + blk * 8;
        k_dst[it] = sw;
        v_src[it] = Vg + (size_t)row * LKV + blk * 8;
        v_dst[it] = 32768 + sw;
    }

    // prologue: Q + chunk0 (group 0), chunk1 (group 1)
#pragma unroll
    for (int it = 0; it < 8; it++) {
        int idx = tid + it * 256, row = idx >> 4, blk = idx & 15;
        cpa16(sb + AT_Q + (row * 64 + (((blk ^ row) & 15) << 2)) * 4,
              Qg + (size_t)row * 128 + blk * 8);
    }
    {
        uint32_t base = sb + AT_STG;
#pragma unroll
        for (int it = 0; it < 8; it++) cpa16(base + k_dst[it], k_src[it]);
#pragma unroll
        for (int it = 0; it < 8; it++) cpa16(base + v_dst[it], v_src[it]);
        CP_COMMIT();
    }
    {
        uint32_t base = sb + AT_STG + 65536;
#pragma unroll
        for (int it = 0; it < 8; it++) cpa16(base + k_dst[it], k_src[it] + (size_t)128 * 128);
#pragma unroll
        for (int it = 0; it < 8; it++) cpa16(base + v_dst[it], v_src[it] + 128);
        CP_COMMIT();
    }

    float oacc[4][4][4];
#pragma unroll
    for (int i = 0; i < 4; i++)
#pragma unroll
        for (int j = 0; j < 4; j++)
#pragma unroll
            for (int r = 0; r < 4; r++) oacc[i][j][r] = 0.f;
    float rsum[2][2] = {{0.f, 0.f}, {0.f, 0.f}};

    // ---- wait for Q + chunk0; hoist Q fragments into registers
    CP_WAIT(1);
    __syncthreads();
    unsigned qfr[8][2][4];
#pragma unroll
    for (int ks = 0; ks < 8; ks++) {
        uint32_t qa = q_ro + ((((ks * 2 + ach) ^ ar) & 15) << 4);
#pragma unroll
        for (int i = 0; i < 2; i++) ldsm4(qfr[ks][i], qa + i * 4096);
    }

    const int NC = LKV / 128;
    for (int ci = 0; ci < NC; ci++) {
        if (ci > 0) { CP_WAIT(1); __syncthreads(); }
        const uint32_t stg = sb + AT_STG + (ci & 1) * 65536;
        const uint32_t k_ro = stg + (uint32_t)(wl * 64 + br) * 256;
        const uint32_t v_ro = stg + 32768 + (uint32_t)(wd * 32 + br) * 256;

        // ---- S = Q K^T : warp 32q x 64l
        float sac[2][8][4];
#pragma unroll
        for (int i = 0; i < 2; i++)
#pragma unroll
            for (int j = 0; j < 8; j++)
#pragma unroll
                for (int r = 0; r < 4; r++) sac[i][j][r] = 0.f;
#pragma unroll
        for (int ks = 0; ks < 8; ks++) {
            unsigned bfr[8][2];
            uint32_t ka = k_ro + ((((ks * 2 + bch) ^ br) & 15) << 4);
#pragma unroll
            for (int jp = 0; jp < 4; jp++) {
                unsigned tmp[4];
                ldsm4(tmp, ka + jp * 4096);
                bfr[2*jp][0] = tmp[0]; bfr[2*jp][1] = tmp[1];
                bfr[2*jp+1][0] = tmp[2]; bfr[2*jp+1][1] = tmp[3];
            }
#pragma unroll
            for (int i = 0; i < 2; i++)
#pragma unroll
                for (int j = 0; j < 8; j++)
                    mma_f16(sac[i][j], qfr[ks][i], bfr[j]);
        }

        // ---- P = exp2(S), row sums, store P (half2 words, swQ64)
#pragma unroll
        for (int i = 0; i < 2; i++) {
            int r0 = wq4 * 32 + i * 16 + g;
#pragma unroll
            for (int j = 0; j < 8; j++) {
                int w = wl * 32 + j * 4 + t;
                float p0 = ex2(sac[i][j][0]);
                float p1 = ex2(sac[i][j][1]);
                float p2 = ex2(sac[i][j][2]);
                float p3 = ex2(sac[i][j][3]);
                rsum[i][0] += p0 + p1;
                rsum[i][1] += p2 + p3;
                Ps[swQ64(r0,     w)] = pack2h(p0, p1);
                Ps[swQ64(r0 + 8, w)] = pack2h(p2, p3);
            }
        }
        __syncthreads();

        // ---- O += P V : warp 64q x 32d
#pragma unroll
        for (int ks = 0; ks < 8; ks++) {
            unsigned afr[4][4], bfr[4][2];
            uint32_t pa = p_ro + ((((ks * 2 + ach) ^ ar) & 15) << 4);
#pragma unroll
            for (int i = 0; i < 4; i++) ldsm4(afr[i], pa + i * 4096);
            uint32_t va = v_ro + ((((ks * 2 + bch) ^ br) & 15) << 4);
#pragma unroll
            for (int jp = 0; jp < 2; jp++) {
                unsigned tmp[4];
                ldsm4(tmp, va + jp * 4096);
                bfr[2*jp][0] = tmp[0]; bfr[2*jp][1] = tmp[1];
                bfr[2*jp+1][0] = tmp[2]; bfr[2*jp+1][1] = tmp[3];
            }
#pragma unroll
            for (int i = 0; i < 4; i++)
#pragma unroll
                for (int j = 0; j < 4; j++)
                    mma_f16(oacc[i][j], afr[i], bfr[j]);
        }
        __syncthreads();

        if (ci + 2 < NC) {
            uint32_t base = sb + AT_STG + (ci & 1) * 65536;
            size_t koff = (size_t)(ci + 2) * 128 * 128;
            int voff = (ci + 2) * 128;
#pragma unroll
            for (int it = 0; it < 8; it++) cpa16(base + k_dst[it], k_src[it] + koff);
#pragma unroll
            for (int it = 0; it < 8; it++) cpa16(base + v_dst[it], v_src[it] + voff);
        }
        CP_COMMIT();
    }

    // ---- row-sum reduction (ls overlays P region)
    float* ls = (float*)Ps;
#pragma unroll
    for (int i = 0; i < 2; i++)
#pragma unroll
        for (int h = 0; h < 2; h++) {
            float v = rsum[i][h];
            v += __shfl_xor_sync(0xffffffffu, v, 1);
            v += __shfl_xor_sync(0xffffffffu, v, 2);
            rsum[i][h] = v;
        }
    if (t == 0) {
#pragma unroll
        for (int i = 0; i < 2; i++) {
            int r = wq4 * 32 + i * 16 + g;
            ls[wl * 128 + r]     = rsum[i][0];
            ls[wl * 128 + r + 8] = rsum[i][1];
        }
    }
    __syncthreads();

    // ---- epilogue: normalize, scatter (half2)
    int bb2 = bh >> 3, h = bh & 7;
#pragma unroll
    for (int i = 0; i < 4; i++) {
#pragma unroll
        for (int half = 0; half < 2; half++) {
            int r = wq2 * 64 + i * 16 + g + half * 8;
            float inv = 1.f / (ls[r] + ls[128 + r]);
            size_t rowoff = ((size_t)(bb2 * 512 + q0 + r)) * 1024 + h * 128;
#pragma unroll
            for (int j = 0; j < 4; j++) {
                int cc = wd * 32 + j * 8 + 2 * t;
                *(unsigned*)(AO + rowoff + cc) =
                    pack2h(oacc[i][j][half * 2] * inv, oacc[i][j][half * 2 + 1] * inv);
            }
        }
    }
}

// ---------------------------------------------------------------------------
// Launcher. gemm_h<0> slices at launch indices 5..8 so ncu -s 5 samples it.
// ---------------------------------------------------------------------------
extern "C" void kernel_launch(void* const* d_in, const int* in_sizes, int n_in,
                              void* d_out, int out_size)
{
    (void)in_sizes; (void)n_in; (void)out_size;
    const float* latent   = (const float*)d_in[0];
    const float* inpkv    = (const float*)d_in[1];
    const float* W_Q      = (const float*)d_in[2];
    const float* W_K      = (const float*)d_in[3];
    const float* W_V      = (const float*)d_in[4];
    const float* W_O      = (const float*)d_in[5];
    const float* ln_lat_g = (const float*)d_in[6];
    const float* ln_lat_b = (const float*)d_in[7];
    const float* ln_in_g  = (const float*)d_in[8];
    const float* ln_in_b  = (const float*)d_in[9];
    float* out = (float*)d_out;

    float *p_mukv, *p_rskv, *p_muq, *p_rsq, *p_vb, *p_vg, *p_vbq, *p_vgq, *p_vbp, *p_vgp;
    void *p_Xkv, *p_Xq, *p_Q, *p_K, *p_Vt, *p_AO, *p_WTkv, *p_WTq, *p_WTo;
    cudaGetSymbolAddress((void**)&p_mukv, g_mu_kv);
    cudaGetSymbolAddress((void**)&p_rskv, g_rs_kv);
    cudaGetSymbolAddress((void**)&p_muq,  g_mu_q);
    cudaGetSymbolAddress((void**)&p_rsq,  g_rs_q);
    cudaGetSymbolAddress(&p_Xkv,  g_Xkv4);
    cudaGetSymbolAddress(&p_Xq,   g_Xq4);
    cudaGetSymbolAddress(&p_Q,    g_Qb4);
    cudaGetSymbolAddress(&p_K,    g_Kb4);
    cudaGetSymbolAddress(&p_Vt,   g_Vt4);
    cudaGetSymbolAddress(&p_AO,   g_AO4);
    cudaGetSymbolAddress(&p_WTkv, g_WTkv4);
    cudaGetSymbolAddress(&p_WTq,  g_WTq4);
    cudaGetSymbolAddress(&p_WTo,  g_WTo4);
    cudaGetSymbolAddress((void**)&p_vb,  g_vb);
    cudaGetSymbolAddress((void**)&p_vg,  g_vg);
    cudaGetSymbolAddress((void**)&p_vbq, g_vbq);
    cudaGetSymbolAddress((void**)&p_vgq, g_vgq);
    cudaGetSymbolAddress((void**)&p_vbp, g_vbp);
    cudaGetSymbolAddress((void**)&p_vgp, g_vgp);

    cudaFuncSetAttribute(gemm_h<0>, cudaFuncAttributeMaxDynamicSharedMemorySize, G_SMEM);
    cudaFuncSetAttribute(gemm_h<1>, cudaFuncAttributeMaxDynamicSharedMemorySize, G_SMEM);
    cudaFuncSetAttribute(gemm_h<2>, cudaFuncAttributeMaxDynamicSharedMemorySize, G_SMEM);
    cudaFuncSetAttribute(attn_h,    cudaFuncAttributeMaxDynamicSharedMemorySize, A_SMEM_BYTES);

    dim3 tb(32, 8);
    // 0: KV row stats + half copy
    rowstats_kernel<<<MKV / 8, 256>>>(inpkv, (__half*)p_Xkv, p_mukv, p_rskv, CH_IN);
    // 1,2: K|V weight transposes (gamma folded)
    wtrans_kernel<<<dim3(32, 24), tb>>>(W_K, (__half*)p_WTkv,              768, 1024, ln_in_g);
    wtrans_kernel<<<dim3(32, 24), tb>>>(W_V, (__half*)p_WTkv + 1024 * 768, 768, 1024, ln_in_g);
    // 3,4: LN fold vectors for K|V (split-K + reduce)
    vbvg_part<<<dim3(32, 6), 256>>>(W_K, W_V, ln_in_g, ln_in_b, p_vbp, p_vgp, 2048);
    vbvg_reduce<<<8, 256>>>(p_vbp, p_vgp, p_vb, p_vg, 6, 2048);
    // 5..8: K|V projection, 4 m-slices  <-- profiler lands on index 5
    for (int s = 0; s < 4; s++)
        gemm_h<0><<<dim3(8, 256), 256, G_SMEM>>>((const __half*)p_Xkv, (const __half*)p_WTkv,
                                                 p_mukv, p_rskv, p_vb, p_vg, nullptr,
                                                 CH_IN, s * 256);
    // 9: Q row stats + half copy
    rowstats_kernel<<<MQ / 8, 256>>>(latent, (__half*)p_Xq, p_muq, p_rsq, CH_LAT);
    // 10-12: Q weight prep
    wtrans_kernel<<<dim3(32, 32), tb>>>(W_Q, (__half*)p_WTq, 1024, 1024, ln_lat_g);
    vbvg_part<<<dim3(16, 8), 256>>>(W_Q, W_Q, ln_lat_g, ln_lat_b, p_vbp, p_vgp, 1024);
    vbvg_reduce<<<4, 256>>>(p_vbp, p_vgp, p_vbq, p_vgq, 8, 1024);
    // 13: Q projection
    gemm_h<1><<<dim3(4, 32), 256, G_SMEM>>>((const __half*)p_Xq, (const __half*)p_WTq,
                                            p_muq, p_rsq, p_vbq, p_vgq, nullptr, CH_LAT, 0);
    // 14: flash attention
    attn_h<<<dim3(4, BH), 256, A_SMEM_BYTES>>>((const __half*)p_Q, (const __half*)p_K,
                                               (const __half*)p_Vt, (__half*)p_AO);
    // 15: O weight transpose
    wtrans_kernel<<<dim3(32, 32), tb>>>(W_O, (__half*)p_WTo, 1024, 1024, nullptr);
    // 16: output projection (float out)
    gemm_h<2><<<dim3(4, 32), 256, G_SMEM>>>((const __half*)p_AO, (const __half*)p_WTo,
                                            nullptr, nullptr, nullptr, nullptr, out, 1024, 0);
}

// round 13
// speedup vs baseline: 1.0200x; 1.0200x over previous
#include <cuda_runtime.h>
#include <cuda_fp16.h>
#include <math.h>
#include <stdint.h>

// ---------------------------------------------------------------------------
// Problem dims
// ---------------------------------------------------------------------------
#define NB      8
#define LQ      512
#define LKV     16384
#define CH_LAT  1024
#define CH_IN   768
#define DH      128
#define NH      8
#define BH      (NB*NH)        // 64
#define MKV     (NB*LKV)       // 131072
#define MQ      (NB*LQ)        // 4096

// 1/sqrt(128) * log2(e)  (folded into Q; softmax uses exp2)
#define QSCALE  (0.08838834764831845f * 1.4426950408889634f)

// ---------------------------------------------------------------------------
// Scratch (device globals; uint4-typed for 16B alignment, cast to __half)
// ---------------------------------------------------------------------------
__device__ float g_mu_kv[MKV], g_rs_kv[MKV];
__device__ float g_mu_q[MQ],   g_rs_q[MQ];
__device__ uint4 g_Xkv4[(size_t)MKV*CH_IN/8];    // half copy of input_kv
__device__ uint4 g_Xq4 [(size_t)MQ*CH_LAT/8];    // half copy of latent
__device__ uint4 g_Qb4 [(size_t)BH*LQ*DH/8];     // half [bh][q][d], QSCALE folded
__device__ uint4 g_Kb4 [(size_t)BH*LKV*DH/8];    // half [bh][l][d]
__device__ uint4 g_Vt4 [(size_t)BH*DH*LKV/8];    // half [bh][d][l]
__device__ uint4 g_AO4 [(size_t)MQ*1024/8];      // half [b*512+q][h*128+d]
__device__ uint4 g_WTkv4[2048*768/8];            // half (gamma*W)^T; <1024: K, >=1024: V
__device__ uint4 g_WTq4 [1024*1024/8];
__device__ uint4 g_WTo4 [1024*1024/8];
__device__ float g_vb[2048], g_vg[2048];         // beta^T W, gamma^T W (KV)
__device__ float g_vbq[1024], g_vgq[1024];       // (Q)
__device__ float g_vbp[8*2048], g_vgp[8*2048];   // split-K partials

// ---------------------------------------------------------------------------
// helpers
// ---------------------------------------------------------------------------
__device__ __forceinline__ float ex2(float x) {
    float y; asm("ex2.approx.ftz.f32 %0, %1;" : "=f"(y) : "f"(x)); return y;
}
__device__ __forceinline__ unsigned pack2h(float a, float b) {
    __half2 h = __floats2half2_rn(a, b);
    return *(unsigned*)&h;
}
__device__ __forceinline__ uint32_t smem_u32(const void* p) {
    uint32_t a;
    asm("{ .reg .u64 t; cvta.to.shared.u64 t, %1; cvt.u32.u64 %0, t; }" : "=r"(a) : "l"(p));
    return a;
}
__device__ __forceinline__ void cpa16(uint32_t dst, const void* src) {
    asm volatile("cp.async.cg.shared.global [%0], [%1], 16;" :: "r"(dst), "l"(src));
}
#define CP_COMMIT() asm volatile("cp.async.commit_group;")
#define CP_WAIT(N)  asm volatile("cp.async.wait_group %0;" :: "n"(N))

__device__ __forceinline__ void mma_f16(float* c, const unsigned* a, const unsigned* b) {
    asm volatile(
        "mma.sync.aligned.m16n8k16.row.col.f32.f16.f16.f32 "
        "{%0,%1,%2,%3}, {%4,%5,%6,%7}, {%8,%9}, {%0,%1,%2,%3};\n"
        : "+f"(c[0]), "+f"(c[1]), "+f"(c[2]), "+f"(c[3])
        : "r"(a[0]), "r"(a[1]), "r"(a[2]), "r"(a[3]), "r"(b[0]), "r"(b[1]));
}
__device__ __forceinline__ void ldsm4(unsigned* r, uint32_t a) {
    asm volatile("ldmatrix.sync.aligned.m8n8.x4.shared.b16 {%0,%1,%2,%3}, [%4];"
                 : "=r"(r[0]), "=r"(r[1]), "=r"(r[2]), "=r"(r[3]) : "r"(a));
}

// Swizzled word (b32 = half2) offsets
__device__ __forceinline__ int swQ64(int row, int w) {   // 64-word (128-half) rows
    return row * 64 + ((((w >> 2) ^ row) & 15) << 2) + (w & 3);
}

// ---------------------------------------------------------------------------
// Row stats + half copy (one warp per row)
// ---------------------------------------------------------------------------
__global__ void rowstats_kernel(const float* __restrict__ X, __half* __restrict__ Xh,
                                float* __restrict__ mu, float* __restrict__ rs, int cols)
{
    int row  = blockIdx.x * 8 + (threadIdx.x >> 5);
    int lane = threadIdx.x & 31;
    const float* xr = X + (size_t)row * cols;
    __half* xo = Xh + (size_t)row * cols;
    float s = 0.f, s2 = 0.f;
    for (int c = lane; c < cols; c += 32) {
        float v = xr[c];
        xo[c] = __float2half_rn(v);
        s += v; s2 += v * v;
    }
#pragma unroll
    for (int o = 16; o; o >>= 1) {
        s  += __shfl_xor_sync(0xffffffffu, s,  o);
        s2 += __shfl_xor_sync(0xffffffffu, s2, o);
    }
    if (lane == 0) {
        float m = s / cols;
        float var = fmaxf(s2 / cols - m * m, 0.f);
        mu[row] = m; rs[row] = rsqrtf(var + 1e-5f);
    }
}

// ---------------------------------------------------------------------------
// Weight transpose: out[c][r] = half(in[r][c] * (scale?scale[r]:1))
// ---------------------------------------------------------------------------
__global__ void wtrans_kernel(const float* __restrict__ in, __half* __restrict__ out,
                              int R, int C, const float* __restrict__ scale)
{
    __shared__ float t[32][33];
    int c0 = blockIdx.x * 32, r0 = blockIdx.y * 32;
    int tx = threadIdx.x, ty = threadIdx.y;
#pragma unroll
    for (int j = 0; j < 4; j++) {
        int r = r0 + ty + j * 8;
        float v = in[(size_t)r * C + c0 + tx];
        if (scale) v *= scale[r];
        t[ty + j * 8][tx] = v;
    }
    __syncthreads();
#pragma unroll
    for (int j = 0; j < 4; j++)
        out[(size_t)(c0 + ty + j * 8) * R + r0 + tx] = __float2half_rn(t[tx][ty + j * 8]);
}

// ---------------------------------------------------------------------------
// vb/vg fold vectors: split-K partials + reduce.
// ---------------------------------------------------------------------------
__global__ void vbvg_part(const float* __restrict__ W0, const float* __restrict__ W1,
                          const float* __restrict__ gamma, const float* __restrict__ beta,
                          float* __restrict__ vbp, float* __restrict__ vgp, int N)
{
    __shared__ float sbv[4][64], sgv[4][64];
    int nl = threadIdx.x & 63;
    int n = blockIdx.x * 64 + nl;
    int rg = threadIdx.x >> 6;
    int r0 = blockIdx.y * 128;
    const float* W = (n < 1024) ? W0 : W1;
    int nn = n & 1023;
    float sb = 0.f, sg = 0.f;
#pragma unroll 4
    for (int r = r0 + rg; r < r0 + 128; r += 4) {
        float w = W[(size_t)r * 1024 + nn];
        sb += beta[r] * w;
        sg += gamma[r] * w;
    }
    sbv[rg][nl] = sb;
    sgv[rg][nl] = sg;
    __syncthreads();
    if (threadIdx.x < 64) {
        vbp[(size_t)blockIdx.y * N + n] = sbv[0][nl] + sbv[1][nl] + sbv[2][nl] + sbv[3][nl];
        vgp[(size_t)blockIdx.y * N + n] = sgv[0][nl] + sgv[1][nl] + sgv[2][nl] + sgv[3][nl];
    }
}

__global__ void vbvg_reduce(const float* __restrict__ vbp, const float* __restrict__ vgp,
                            float* __restrict__ vb, float* __restrict__ vg, int S, int N)
{
    int n = blockIdx.x * 256 + threadIdx.x;
    float a = 0.f, b = 0.f;
    for (int s = 0; s < S; s++) { a += vbp[(size_t)s * N + n]; b += vgp[(size_t)s * N + n]; }
    vb[n] = a; vg[n] = b;
}

// ---------------------------------------------------------------------------
// FP16 GEMM: block 128x256, BK=32, 256 threads (8 warps 2x4), warp 64x64,
// m16n8k16, cp.async 4-stage, ldmatrix fragment loads.
// MODE 0: -> g_Kb half (n<1024) / g_Vt half transposed (n>=1024)
// MODE 1: -> g_Qb half, *QSCALE
// MODE 2: -> float row-major C
// ---------------------------------------------------------------------------
#define G_STAGE 24576
#define G_SMEM  (4*G_STAGE)      // 96KB

template<int MODE>
__global__ __launch_bounds__(256, 1)
void gemm_h(const __half* __restrict__ A, const __half* __restrict__ WT,
            const float* __restrict__ mu, const float* __restrict__ rs,
            const float* __restrict__ vb, const float* __restrict__ vg,
            float* __restrict__ C, int K)
{
    extern __shared__ char sm[];
    const uint32_t sb = smem_u32(sm);
    const int tid = threadIdx.x;
    const int lane = tid & 31, wid = tid >> 5;
    const int wm = wid >> 2, wn = wid & 3;
    const int g = lane >> 2, t = lane & 3;
    const int m0 = blockIdx.y * 128, n0 = blockIdx.x * 256;
    const int KC = K >> 5;

    const __half* Ag = A  + (size_t)m0 * K;
    const __half* Bg = WT + (size_t)n0 * K;

    const __half* a_src[2]; uint32_t a_dst[2];
#pragma unroll
    for (int it = 0; it < 2; it++) {
        int idx = tid + it * 256, row = idx >> 2, blk = idx & 3;
        a_src[it] = Ag + (size_t)row * K + blk * 8;
        a_dst[it] = (row * 16 + ((((blk ^ (row >> 1)) & 3)) << 2)) * 4;
    }
    const __half* b_src[4]; uint32_t b_dst[4];
#pragma unroll
    for (int it = 0; it < 4; it++) {
        int idx = tid + it * 256, row = idx >> 2, blk = idx & 3;
        b_src[it] = Bg + (size_t)row * K + blk * 8;
        b_dst[it] = 8192 + (row * 16 + ((((blk ^ (row >> 1)) & 3)) << 2)) * 4;
    }

    // ldmatrix per-lane geometry
    const int a_row = ((lane >> 3) & 1) * 8 + (lane & 7);
    const int a_ch  = lane >> 4;
    const uint32_t a_ro = (uint32_t)(wm * 64 + a_row) * 64;
    const int a_x   = (a_row >> 1) & 3;
    const int b_row = ((lane >> 4) & 1) * 8 + (lane & 7);
    const int b_ch  = (lane >> 3) & 1;
    const uint32_t b_ro = (uint32_t)(wn * 64 + b_row) * 64;
    const int b_x   = (b_row >> 1) & 3;

    float acc[4][8][4];
#pragma unroll
    for (int i = 0; i < 4; i++)
#pragma unroll
        for (int j = 0; j < 8; j++)
#pragma unroll
            for (int r = 0; r < 4; r++) acc[i][j][r] = 0.f;

#pragma unroll
    for (int s = 0; s < 3; s++) {
        uint32_t base = sb + s * G_STAGE;
        int k0 = s * 32;
#pragma unroll
        for (int it = 0; it < 2; it++) cpa16(base + a_dst[it], a_src[it] + k0);
#pragma unroll
        for (int it = 0; it < 4; it++) cpa16(base + b_dst[it], b_src[it] + k0);
        CP_COMMIT();
    }

    for (int c = 0; c < KC; c++) {
        CP_WAIT(2);
        __syncthreads();
        if (c + 3 < KC) {
            uint32_t base = sb + ((c + 3) & 3) * G_STAGE;
            int k0 = (c + 3) * 32;
#pragma unroll
            for (int it = 0; it < 2; it++) cpa16(base + a_dst[it], a_src[it] + k0);
#pragma unroll
            for (int it = 0; it < 4; it++) cpa16(base + b_dst[it], b_src[it] + k0);
        }
        CP_COMMIT();

        const uint32_t abase = sb + (c & 3) * G_STAGE;
        const uint32_t bbase = abase + 8192;
#pragma unroll
        for (int ks = 0; ks < 2; ks++) {
            unsigned afr[4][4], bfr[8][2];
            uint32_t aoff = abase + a_ro + ((((ks * 2 + a_ch) ^ a_x) & 3) << 4);
#pragma unroll
            for (int i = 0; i < 4; i++) ldsm4(afr[i], aoff + i * 1024);
            uint32_t boff = bbase + b_ro + ((((ks * 2 + b_ch) ^ b_x) & 3) << 4);
#pragma unroll
            for (int jp = 0; jp < 4; jp++) {
                unsigned tmp[4];
                ldsm4(tmp, boff + jp * 1024);
                bfr[2*jp][0] = tmp[0]; bfr[2*jp][1] = tmp[1];
                bfr[2*jp+1][0] = tmp[2]; bfr[2*jp+1][1] = tmp[3];
            }
#pragma unroll
            for (int i = 0; i < 4; i++)
#pragma unroll
                for (int j = 0; j < 8; j++)
                    mma_f16(acc[i][j], afr[i], bfr[j]);
        }
    }
    CP_WAIT(0);
    __syncthreads();

    // ---- epilogue
    float Rr[8], MR[8];
    if (MODE != 2) {
#pragma unroll
        for (int i = 0; i < 4; i++)
#pragma unroll
            for (int half = 0; half < 2; half++) {
                int r = m0 + wm * 64 + i * 16 + g + half * 8;
                float rv = rs[r];
                Rr[i * 2 + half] = rv;
                MR[i * 2 + half] = mu[r] * rv;
            }
    }
    float vbv[16], vgv[16];
    if (MODE != 2) {
#pragma unroll
        for (int j = 0; j < 8; j++) {
            int cg = n0 + wn * 64 + j * 8 + 2 * t;
            vbv[2*j] = vb[cg]; vbv[2*j+1] = vb[cg+1];
            vgv[2*j] = vg[cg]; vgv[2*j+1] = vg[cg+1];
        }
    }

    const bool vpart = (MODE == 0) && (n0 >= 1024);
    __half* st = (__half*)sm;
    __half* Kb = (__half*)g_Kb4;
    __half* Qb = (__half*)g_Qb4;
    __half* Vt = (__half*)g_Vt4;

#pragma unroll
    for (int i = 0; i < 4; i++) {
#pragma unroll
        for (int j = 0; j < 8; j++) {
#pragma unroll
            for (int half = 0; half < 2; half++) {
                int rl = wm * 64 + i * 16 + g + half * 8;
                int r = m0 + rl;
                int cl = wn * 64 + j * 8 + 2 * t;
                int cg = n0 + cl;
                float v0 = acc[i][j][half * 2 + 0];
                float v1 = acc[i][j][half * 2 + 1];
                if (MODE != 2) {
                    float R = Rr[i * 2 + half], M = MR[i * 2 + half];
                    v0 = R * v0 + vbv[2*j]   - M * vgv[2*j];
                    v1 = R * v1 + vbv[2*j+1] - M * vgv[2*j+1];
                }
                if (MODE == 0) {
                    if (!vpart) {
                        int h = cg >> 7, d = cg & 127;
                        int bb2 = r >> 14, l = r & 16383;
                        unsigned u = pack2h(v0, v1);
                        *(unsigned*)(Kb + ((((size_t)(bb2 * 8 + h)) << 14) + l) * 128 + d) = u;
                    } else {
                        st[cl * 136 + rl]       = __float2half_rn(v0);
                        st[(cl + 1) * 136 + rl] = __float2half_rn(v1);
                    }
                } else if (MODE == 1) {
                    int h = cg >> 7, d = cg & 127;
                    int bb2 = r >> 9, q = r & 511;
                    unsigned u = pack2h(QSCALE * v0, QSCALE * v1);
                    *(unsigned*)(Qb + (((size_t)(bb2 * 8 + h)) * 512 + q) * 128 + d) = u;
                } else {
                    *(float2*)(C + (size_t)r * 1024 + cg) = make_float2(v0, v1);
                }
            }
        }
    }
    if (vpart) {
        __syncthreads();
        int bb2 = m0 >> 14, l0 = m0 & 16383;
#pragma unroll
        for (int cl2 = 0; cl2 < 32; cl2++) {
            int c = wid * 32 + cl2;
            int cg = n0 + c - 1024;
            int h = cg >> 7, d = cg & 127;
            uint2 v = *(const uint2*)&st[c * 136 + lane * 4];
            *(uint2*)(Vt + ((size_t)(bb2 * 8 + h) * 128 + d) * LKV + l0 + lane * 4) = v;
        }
    }
}

// ---------------------------------------------------------------------------
// FP16 flash attention. Br=128, Bc=128, 256 threads, m16n8k16, cp.async
// 2-stage, ldmatrix loads, Q fragments hoisted to registers (loop-invariant).
//   S:  warps 4x2 (q32 x l64);  PV: warps 2x4 (q64 x d32).
// Smem: Q 32KB | stage0 K32+V32 | stage1 K32+V32 | P 32KB (ls overlays P).
// ---------------------------------------------------------------------------
#define AT_Q     0
#define AT_STG   32768
#define AT_P     163840
#define A_SMEM_BYTES 196608

__global__ __launch_bounds__(256, 1)
void attn_h(const __half* __restrict__ Qb, const __half* __restrict__ Kb,
            const __half* __restrict__ Vt, __half* __restrict__ AO)
{
    extern __shared__ char sm[];
    const uint32_t sb = smem_u32(sm);
    const int tid = threadIdx.x;
    const int lane = tid & 31, wid = tid >> 5;
    const int g = lane >> 2, t = lane & 3;
    const int bh = blockIdx.y;
    const int q0 = blockIdx.x * 128;

    const int wq4 = wid & 3, wl = wid >> 2;   // S phase: q 32, l 64
    const int wq2 = wid & 1, wd = wid >> 1;   // PV phase: q 64, d 32

    const __half* Qg = Qb + ((size_t)bh * LQ + q0) * DH;
    const __half* Kg = Kb + (size_t)bh * LKV * DH;
    const __half* Vg = Vt + (size_t)bh * DH * LKV;

    unsigned* Ps = (unsigned*)(sm + AT_P);

    // ldmatrix per-lane geometry
    const int ar = ((lane >> 3) & 1) * 8 + (lane & 7);
    const int ach = lane >> 4;
    const int br = ((lane >> 4) & 1) * 8 + (lane & 7);
    const int bch = (lane >> 3) & 1;
    const uint32_t q_ro = sb + AT_Q + (uint32_t)(wq4 * 32 + ar) * 256;
    const uint32_t p_ro = sb + AT_P + (uint32_t)(wq2 * 64 + ar) * 256;

    // staging assignments
    const __half* k_src[8]; uint32_t k_dst[8];
    const __half* v_src[8]; uint32_t v_dst[8];
#pragma unroll
    for (int it = 0; it < 8; it++) {
        int idx = tid + it * 256, row = idx >> 4, blk = idx & 15;
        uint32_t sw = (row * 64 + (((blk ^ row) & 15) << 2)) * 4;
        k_src[it] = Kg + (size_t)row * 128 + blk * 8;
        k_dst[it] = sw;
        v_src[it] = Vg + (size_t)row * LKV + blk * 8;
        v_dst[it] = 32768 + sw;
    }

    // prologue: Q + chunk0 (group 0), chunk1 (group 1)
#pragma unroll
    for (int it = 0; it < 8; it++) {
        int idx = tid + it * 256, row = idx >> 4, blk = idx & 15;
        cpa16(sb + AT_Q + (row * 64 + (((blk ^ row) & 15) << 2)) * 4,
              Qg + (size_t)row * 128 + blk * 8);
    }
    {
        uint32_t base = sb + AT_STG;
#pragma unroll
        for (int it = 0; it < 8; it++) cpa16(base + k_dst[it], k_src[it]);
#pragma unroll
        for (int it = 0; it < 8; it++) cpa16(base + v_dst[it], v_src[it]);
        CP_COMMIT();
    }
    {
        uint32_t base = sb + AT_STG + 65536;
#pragma unroll
        for (int it = 0; it < 8; it++) cpa16(base + k_dst[it], k_src[it] + (size_t)128 * 128);
#pragma unroll
        for (int it = 0; it < 8; it++) cpa16(base + v_dst[it], v_src[it] + 128);
        CP_COMMIT();
    }

    float oacc[4][4][4];
#pragma unroll
    for (int i = 0; i < 4; i++)
#pragma unroll
        for (int j = 0; j < 4; j++)
#pragma unroll
            for (int r = 0; r < 4; r++) oacc[i][j][r] = 0.f;
    float rsum[2][2] = {{0.f, 0.f}, {0.f, 0.f}};

    // ---- wait for Q + chunk0; hoist Q fragments into registers
    CP_WAIT(1);
    __syncthreads();
    unsigned qfr[8][2][4];
#pragma unroll
    for (int ks = 0; ks < 8; ks++) {
        uint32_t qa = q_ro + ((((ks * 2 + ach) ^ ar) & 15) << 4);
#pragma unroll
        for (int i = 0; i < 2; i++) ldsm4(qfr[ks][i], qa + i * 4096);
    }

    const int NC = LKV / 128;
    for (int ci = 0; ci < NC; ci++) {
        if (ci > 0) { CP_WAIT(1); __syncthreads(); }
        const uint32_t stg = sb + AT_STG + (ci & 1) * 65536;
        const uint32_t k_ro = stg + (uint32_t)(wl * 64 + br) * 256;
        const uint32_t v_ro = stg + 32768 + (uint32_t)(wd * 32 + br) * 256;

        // ---- S = Q K^T : warp 32q x 64l
        float sac[2][8][4];
#pragma unroll
        for (int i = 0; i < 2; i++)
#pragma unroll
            for (int j = 0; j < 8; j++)
#pragma unroll
                for (int r = 0; r < 4; r++) sac[i][j][r] = 0.f;
#pragma unroll
        for (int ks = 0; ks < 8; ks++) {
            unsigned bfr[8][2];
            uint32_t ka = k_ro + ((((ks * 2 + bch) ^ br) & 15) << 4);
#pragma unroll
            for (int jp = 0; jp < 4; jp++) {
                unsigned tmp[4];
                ldsm4(tmp, ka + jp * 4096);
                bfr[2*jp][0] = tmp[0]; bfr[2*jp][1] = tmp[1];
                bfr[2*jp+1][0] = tmp[2]; bfr[2*jp+1][1] = tmp[3];
            }
#pragma unroll
            for (int i = 0; i < 2; i++)
#pragma unroll
                for (int j = 0; j < 8; j++)
                    mma_f16(sac[i][j], qfr[ks][i], bfr[j]);
        }

        // ---- P = exp2(S), row sums, store P (half2 words, swQ64)
#pragma unroll
        for (int i = 0; i < 2; i++) {
            int r0 = wq4 * 32 + i * 16 + g;
#pragma unroll
            for (int j = 0; j < 8; j++) {
                int w = wl * 32 + j * 4 + t;
                float p0 = ex2(sac[i][j][0]);
                float p1 = ex2(sac[i][j][1]);
                float p2 = ex2(sac[i][j][2]);
                float p3 = ex2(sac[i][j][3]);
                rsum[i][0] += p0 + p1;
                rsum[i][1] += p2 + p3;
                Ps[swQ64(r0,     w)] = pack2h(p0, p1);
                Ps[swQ64(r0 + 8, w)] = pack2h(p2, p3);
            }
        }
        __syncthreads();

        // ---- O += P V : warp 64q x 32d
#pragma unroll
        for (int ks = 0; ks < 8; ks++) {
            unsigned afr[4][4], bfr[4][2];
            uint32_t pa = p_ro + ((((ks * 2 + ach) ^ ar) & 15) << 4);
#pragma unroll
            for (int i = 0; i < 4; i++) ldsm4(afr[i], pa + i * 4096);
            uint32_t va = v_ro + ((((ks * 2 + bch) ^ br) & 15) << 4);
#pragma unroll
            for (int jp = 0; jp < 2; jp++) {
                unsigned tmp[4];
                ldsm4(tmp, va + jp * 4096);
                bfr[2*jp][0] = tmp[0]; bfr[2*jp][1] = tmp[1];
                bfr[2*jp+1][0] = tmp[2]; bfr[2*jp+1][1] = tmp[3];
            }
#pragma unroll
            for (int i = 0; i < 4; i++)
#pragma unroll
                for (int j = 0; j < 4; j++)
                    mma_f16(oacc[i][j], afr[i], bfr[j]);
        }
        __syncthreads();

        if (ci + 2 < NC) {
            uint32_t base = sb + AT_STG + (ci & 1) * 65536;
            size_t koff = (size_t)(ci + 2) * 128 * 128;
            int voff = (ci + 2) * 128;
#pragma unroll
            for (int it = 0; it < 8; it++) cpa16(base + k_dst[it], k_src[it] + koff);
#pragma unroll
            for (int it = 0; it < 8; it++) cpa16(base + v_dst[it], v_src[it] + voff);
        }
        CP_COMMIT();
    }

    // ---- row-sum reduction (ls overlays P region)
    float* ls = (float*)Ps;
#pragma unroll
    for (int i = 0; i < 2; i++)
#pragma unroll
        for (int h = 0; h < 2; h++) {
            float v = rsum[i][h];
            v += __shfl_xor_sync(0xffffffffu, v, 1);
            v += __shfl_xor_sync(0xffffffffu, v, 2);
            rsum[i][h] = v;
        }
    if (t == 0) {
#pragma unroll
        for (int i = 0; i < 2; i++) {
            int r = wq4 * 32 + i * 16 + g;
            ls[wl * 128 + r]     = rsum[i][0];
            ls[wl * 128 + r + 8] = rsum[i][1];
        }
    }
    __syncthreads();

    // ---- epilogue: normalize, scatter (half2)
    int bb2 = bh >> 3, h = bh & 7;
#pragma unroll
    for (int i = 0; i < 4; i++) {
#pragma unroll
        for (int half = 0; half < 2; half++) {
            int r = wq2 * 64 + i * 16 + g + half * 8;
            float inv = 1.f / (ls[r] + ls[128 + r]);
            size_t rowoff = ((size_t)(bb2 * 512 + q0 + r)) * 1024 + h * 128;
#pragma unroll
            for (int j = 0; j < 4; j++) {
                int cc = wd * 32 + j * 8 + 2 * t;
                *(unsigned*)(AO + rowoff + cc) =
                    pack2h(oacc[i][j][half * 2] * inv, oacc[i][j][half * 2 + 1] * inv);
            }
        }
    }
}

// ---------------------------------------------------------------------------
// Launcher. KV GEMM is a single launch at index 5 (ncu -s 5 lands on it).
// ---------------------------------------------------------------------------
extern "C" void kernel_launch(void* const* d_in, const int* in_sizes, int n_in,
                              void* d_out, int out_size)
{
    (void)in_sizes; (void)n_in; (void)out_size;
    const float* latent   = (const float*)d_in[0];
    const float* inpkv    = (const float*)d_in[1];
    const float* W_Q      = (const float*)d_in[2];
    const float* W_K      = (const float*)d_in[3];
    const float* W_V      = (const float*)d_in[4];
    const float* W_O      = (const float*)d_in[5];
    const float* ln_lat_g = (const float*)d_in[6];
    const float* ln_lat_b = (const float*)d_in[7];
    const float* ln_in_g  = (const float*)d_in[8];
    const float* ln_in_b  = (const float*)d_in[9];
    float* out = (float*)d_out;

    float *p_mukv, *p_rskv, *p_muq, *p_rsq, *p_vb, *p_vg, *p_vbq, *p_vgq, *p_vbp, *p_vgp;
    void *p_Xkv, *p_Xq, *p_Q, *p_K, *p_Vt, *p_AO, *p_WTkv, *p_WTq, *p_WTo;
    cudaGetSymbolAddress((void**)&p_mukv, g_mu_kv);
    cudaGetSymbolAddress((void**)&p_rskv, g_rs_kv);
    cudaGetSymbolAddress((void**)&p_muq,  g_mu_q);
    cudaGetSymbolAddress((void**)&p_rsq,  g_rs_q);
    cudaGetSymbolAddress(&p_Xkv,  g_Xkv4);
    cudaGetSymbolAddress(&p_Xq,   g_Xq4);
    cudaGetSymbolAddress(&p_Q,    g_Qb4);
    cudaGetSymbolAddress(&p_K,    g_Kb4);
    cudaGetSymbolAddress(&p_Vt,   g_Vt4);
    cudaGetSymbolAddress(&p_AO,   g_AO4);
    cudaGetSymbolAddress(&p_WTkv, g_WTkv4);
    cudaGetSymbolAddress(&p_WTq,  g_WTq4);
    cudaGetSymbolAddress(&p_WTo,  g_WTo4);
    cudaGetSymbolAddress((void**)&p_vb,  g_vb);
    cudaGetSymbolAddress((void**)&p_vg,  g_vg);
    cudaGetSymbolAddress((void**)&p_vbq, g_vbq);
    cudaGetSymbolAddress((void**)&p_vgq, g_vgq);
    cudaGetSymbolAddress((void**)&p_vbp, g_vbp);
    cudaGetSymbolAddress((void**)&p_vgp, g_vgp);

    cudaFuncSetAttribute(gemm_h<0>, cudaFuncAttributeMaxDynamicSharedMemorySize, G_SMEM);
    cudaFuncSetAttribute(gemm_h<1>, cudaFuncAttributeMaxDynamicSharedMemorySize, G_SMEM);
    cudaFuncSetAttribute(gemm_h<2>, cudaFuncAttributeMaxDynamicSharedMemorySize, G_SMEM);
    cudaFuncSetAttribute(attn_h,    cudaFuncAttributeMaxDynamicSharedMemorySize, A_SMEM_BYTES);

    dim3 tb(32, 8);
    // 0: KV row stats + half copy
    rowstats_kernel<<<MKV / 8, 256>>>(inpkv, (__half*)p_Xkv, p_mukv, p_rskv, CH_IN);
    // 1,2: K|V weight transposes (gamma folded)
    wtrans_kernel<<<dim3(32, 24), tb>>>(W_K, (__half*)p_WTkv,              768, 1024, ln_in_g);
    wtrans_kernel<<<dim3(32, 24), tb>>>(W_V, (__half*)p_WTkv + 1024 * 768, 768, 1024, ln_in_g);
    // 3,4: LN fold vectors for K|V (split-K + reduce)
    vbvg_part<<<dim3(32, 6), 256>>>(W_K, W_V, ln_in_g, ln_in_b, p_vbp, p_vgp, 2048);
    vbvg_reduce<<<8, 256>>>(p_vbp, p_vgp, p_vb, p_vg, 6, 2048);
    // 5: K|V projection (single launch)  <-- profiler lands here
    gemm_h<0><<<dim3(8, 1024), 256, G_SMEM>>>((const __half*)p_Xkv, (const __half*)p_WTkv,
                                              p_mukv, p_rskv, p_vb, p_vg, nullptr, CH_IN);
    // 6: Q row stats + half copy
    rowstats_kernel<<<MQ / 8, 256>>>(latent, (__half*)p_Xq, p_muq, p_rsq, CH_LAT);
    // 7-9: Q weight prep
    wtrans_kernel<<<dim3(32, 32), tb>>>(W_Q, (__half*)p_WTq, 1024, 1024, ln_lat_g);
    vbvg_part<<<dim3(16, 8), 256>>>(W_Q, W_Q, ln_lat_g, ln_lat_b, p_vbp, p_vgp, 1024);
    vbvg_reduce<<<4, 256>>>(p_vbp, p_vgp, p_vbq, p_vgq, 8, 1024);
    // 10: Q projection
    gemm_h<1><<<dim3(4, 32), 256, G_SMEM>>>((const __half*)p_Xq, (const __half*)p_WTq,
                                            p_muq, p_rsq, p_vbq, p_vgq, nullptr, CH_LAT);
    // 11: flash attention
    attn_h<<<dim3(4, BH), 256, A_SMEM_BYTES>>>((const __half*)p_Q, (const __half*)p_K,
                                               (const __half*)p_Vt, (__half*)p_AO);
    // 12: O weight transpose
    wtrans_kernel<<<dim3(32, 32), tb>>>(W_O, (__half*)p_WTo, 1024, 1024, nullptr);
    // 13: output projection (float out)
    gemm_h<2><<<dim3(4, 32), 256, G_SMEM>>>((const __half*)p_AO, (const __half*)p_WTo,
                                            nullptr, nullptr, nullptr, nullptr, out, 1024);
}

// round 14
// speedup vs baseline: 1.0629x; 1.0420x over previous
#include <cuda_runtime.h>
#include <cuda_fp16.h>
#include <math.h>
#include <stdint.h>

// ---------------------------------------------------------------------------
// Problem dims
// ---------------------------------------------------------------------------
#define NB      8
#define LQ      512
#define LKV     16384
#define CH_LAT  1024
#define CH_IN   768
#define DH      128
#define NH      8
#define BH      (NB*NH)        // 64
#define MKV     (NB*LKV)       // 131072
#define MQ      (NB*LQ)        // 4096

// 1/sqrt(128) * log2(e)  (folded into Q; softmax uses exp2)
#define QSCALE  (0.08838834764831845f * 1.4426950408889634f)

// ---------------------------------------------------------------------------
// Scratch (device globals; uint4-typed for 16B alignment, cast to __half)
// ---------------------------------------------------------------------------
__device__ float g_mu_kv[MKV], g_rs_kv[MKV];
__device__ float g_mu_q[MQ],   g_rs_q[MQ];
__device__ uint4 g_Xkv4[(size_t)MKV*CH_IN/8];    // half copy of input_kv
__device__ uint4 g_Xq4 [(size_t)MQ*CH_LAT/8];    // half copy of latent
__device__ uint4 g_Qb4 [(size_t)BH*LQ*DH/8];     // half [bh][q][d], QSCALE folded
__device__ uint4 g_Kb4 [(size_t)BH*LKV*DH/8];    // half [bh][l][d]
__device__ uint4 g_Vt4 [(size_t)BH*DH*LKV/8];    // half [bh][d][l]
__device__ uint4 g_AO4 [(size_t)MQ*1024/8];      // half [b*512+q][h*128+d]
__device__ uint4 g_WTkv4[2048*768/8];            // half (gamma*W)^T; <1024: K, >=1024: V
__device__ uint4 g_WTq4 [1024*1024/8];
__device__ uint4 g_WTo4 [1024*1024/8];
__device__ float g_vb[2048], g_vg[2048];         // beta^T W, gamma^T W (KV)
__device__ float g_vbq[1024], g_vgq[1024];       // (Q)
__device__ float g_vbp[8*2048], g_vgp[8*2048];   // split-K partials

// ---------------------------------------------------------------------------
// helpers
// ---------------------------------------------------------------------------
__device__ __forceinline__ float ex2(float x) {
    float y; asm("ex2.approx.ftz.f32 %0, %1;" : "=f"(y) : "f"(x)); return y;
}
__device__ __forceinline__ unsigned pack2h(float a, float b) {
    __half2 h = __floats2half2_rn(a, b);
    return *(unsigned*)&h;
}
__device__ __forceinline__ uint32_t smem_u32(const void* p) {
    uint32_t a;
    asm("{ .reg .u64 t; cvta.to.shared.u64 t, %1; cvt.u32.u64 %0, t; }" : "=r"(a) : "l"(p));
    return a;
}
__device__ __forceinline__ void cpa16(uint32_t dst, const void* src) {
    asm volatile("cp.async.cg.shared.global [%0], [%1], 16;" :: "r"(dst), "l"(src));
}
#define CP_COMMIT() asm volatile("cp.async.commit_group;")
#define CP_WAIT(N)  asm volatile("cp.async.wait_group %0;" :: "n"(N))

__device__ __forceinline__ void mma_f16(float* c, const unsigned* a, const unsigned* b) {
    asm volatile(
        "mma.sync.aligned.m16n8k16.row.col.f32.f16.f16.f32 "
        "{%0,%1,%2,%3}, {%4,%5,%6,%7}, {%8,%9}, {%0,%1,%2,%3};\n"
        : "+f"(c[0]), "+f"(c[1]), "+f"(c[2]), "+f"(c[3])
        : "r"(a[0]), "r"(a[1]), "r"(a[2]), "r"(a[3]), "r"(b[0]), "r"(b[1]));
}
__device__ __forceinline__ void ldsm4(unsigned* r, uint32_t a) {
    asm volatile("ldmatrix.sync.aligned.m8n8.x4.shared.b16 {%0,%1,%2,%3}, [%4];"
                 : "=r"(r[0]), "=r"(r[1]), "=r"(r[2]), "=r"(r[3]) : "r"(a));
}

// Swizzled word (b32 = half2) offsets
__device__ __forceinline__ int swQ64(int row, int w) {   // 64-word (128-half) rows
    return row * 64 + ((((w >> 2) ^ row) & 15) << 2) + (w & 3);
}

// ---------------------------------------------------------------------------
// Row stats + half copy (one warp per row)
// ---------------------------------------------------------------------------
__global__ void rowstats_kernel(const float* __restrict__ X, __half* __restrict__ Xh,
                                float* __restrict__ mu, float* __restrict__ rs, int cols)
{
    int row  = blockIdx.x * 8 + (threadIdx.x >> 5);
    int lane = threadIdx.x & 31;
    const float* xr = X + (size_t)row * cols;
    __half* xo = Xh + (size_t)row * cols;
    float s = 0.f, s2 = 0.f;
    for (int c = lane; c < cols; c += 32) {
        float v = xr[c];
        xo[c] = __float2half_rn(v);
        s += v; s2 += v * v;
    }
#pragma unroll
    for (int o = 16; o; o >>= 1) {
        s  += __shfl_xor_sync(0xffffffffu, s,  o);
        s2 += __shfl_xor_sync(0xffffffffu, s2, o);
    }
    if (lane == 0) {
        float m = s / cols;
        float var = fmaxf(s2 / cols - m * m, 0.f);
        mu[row] = m; rs[row] = rsqrtf(var + 1e-5f);
    }
}

// ---------------------------------------------------------------------------
// Weight transpose: out[c][r] = half(in[r][c] * (scale?scale[r]:1))
// ---------------------------------------------------------------------------
__global__ void wtrans_kernel(const float* __restrict__ in, __half* __restrict__ out,
                              int R, int C, const float* __restrict__ scale)
{
    __shared__ float t[32][33];
    int c0 = blockIdx.x * 32, r0 = blockIdx.y * 32;
    int tx = threadIdx.x, ty = threadIdx.y;
#pragma unroll
    for (int j = 0; j < 4; j++) {
        int r = r0 + ty + j * 8;
        float v = in[(size_t)r * C + c0 + tx];
        if (scale) v *= scale[r];
        t[ty + j * 8][tx] = v;
    }
    __syncthreads();
#pragma unroll
    for (int j = 0; j < 4; j++)
        out[(size_t)(c0 + ty + j * 8) * R + r0 + tx] = __float2half_rn(t[tx][ty + j * 8]);
}

// ---------------------------------------------------------------------------
// vb/vg fold vectors: split-K partials + reduce.
// ---------------------------------------------------------------------------
__global__ void vbvg_part(const float* __restrict__ W0, const float* __restrict__ W1,
                          const float* __restrict__ gamma, const float* __restrict__ beta,
                          float* __restrict__ vbp, float* __restrict__ vgp, int N)
{
    __shared__ float sbv[4][64], sgv[4][64];
    int nl = threadIdx.x & 63;
    int n = blockIdx.x * 64 + nl;
    int rg = threadIdx.x >> 6;
    int r0 = blockIdx.y * 128;
    const float* W = (n < 1024) ? W0 : W1;
    int nn = n & 1023;
    float sb = 0.f, sg = 0.f;
#pragma unroll 4
    for (int r = r0 + rg; r < r0 + 128; r += 4) {
        float w = W[(size_t)r * 1024 + nn];
        sb += beta[r] * w;
        sg += gamma[r] * w;
    }
    sbv[rg][nl] = sb;
    sgv[rg][nl] = sg;
    __syncthreads();
    if (threadIdx.x < 64) {
        vbp[(size_t)blockIdx.y * N + n] = sbv[0][nl] + sbv[1][nl] + sbv[2][nl] + sbv[3][nl];
        vgp[(size_t)blockIdx.y * N + n] = sgv[0][nl] + sgv[1][nl] + sgv[2][nl] + sgv[3][nl];
    }
}

__global__ void vbvg_reduce(const float* __restrict__ vbp, const float* __restrict__ vgp,
                            float* __restrict__ vb, float* __restrict__ vg, int S, int N)
{
    int n = blockIdx.x * 256 + threadIdx.x;
    float a = 0.f, b = 0.f;
    for (int s = 0; s < S; s++) { a += vbp[(size_t)s * N + n]; b += vgp[(size_t)s * N + n]; }
    vb[n] = a; vg[n] = b;
}

// ---------------------------------------------------------------------------
// FP16 GEMM: block 128x256, BK=32, 256 threads (8 warps 2x4), warp 64x64,
// m16n8k16, cp.async 4-stage, ldmatrix fragment loads.
// MODE 0: -> g_Kb half (n<1024) / g_Vt half transposed (n>=1024)
// MODE 1: -> g_Qb half, *QSCALE
// MODE 2: -> float row-major C
// ---------------------------------------------------------------------------
#define G_STAGE 24576
#define G_SMEM  (4*G_STAGE)      // 96KB

template<int MODE>
__global__ __launch_bounds__(256, 1)
void gemm_h(const __half* __restrict__ A, const __half* __restrict__ WT,
            const float* __restrict__ mu, const float* __restrict__ rs,
            const float* __restrict__ vb, const float* __restrict__ vg,
            float* __restrict__ C, int K)
{
    extern __shared__ char sm[];
    const uint32_t sb = smem_u32(sm);
    const int tid = threadIdx.x;
    const int lane = tid & 31, wid = tid >> 5;
    const int wm = wid >> 2, wn = wid & 3;
    const int g = lane >> 2, t = lane & 3;
    const int m0 = blockIdx.y * 128, n0 = blockIdx.x * 256;
    const int KC = K >> 5;

    const __half* Ag = A  + (size_t)m0 * K;
    const __half* Bg = WT + (size_t)n0 * K;

    const __half* a_src[2]; uint32_t a_dst[2];
#pragma unroll
    for (int it = 0; it < 2; it++) {
        int idx = tid + it * 256, row = idx >> 2, blk = idx & 3;
        a_src[it] = Ag + (size_t)row * K + blk * 8;
        a_dst[it] = (row * 16 + ((((blk ^ (row >> 1)) & 3)) << 2)) * 4;
    }
    const __half* b_src[4]; uint32_t b_dst[4];
#pragma unroll
    for (int it = 0; it < 4; it++) {
        int idx = tid + it * 256, row = idx >> 2, blk = idx & 3;
        b_src[it] = Bg + (size_t)row * K + blk * 8;
        b_dst[it] = 8192 + (row * 16 + ((((blk ^ (row >> 1)) & 3)) << 2)) * 4;
    }

    // ldmatrix per-lane geometry
    const int a_row = ((lane >> 3) & 1) * 8 + (lane & 7);
    const int a_ch  = lane >> 4;
    const uint32_t a_ro = (uint32_t)(wm * 64 + a_row) * 64;
    const int a_x   = (a_row >> 1) & 3;
    const int b_row = ((lane >> 4) & 1) * 8 + (lane & 7);
    const int b_ch  = (lane >> 3) & 1;
    const uint32_t b_ro = (uint32_t)(wn * 64 + b_row) * 64;
    const int b_x   = (b_row >> 1) & 3;

    float acc[4][8][4];
#pragma unroll
    for (int i = 0; i < 4; i++)
#pragma unroll
        for (int j = 0; j < 8; j++)
#pragma unroll
            for (int r = 0; r < 4; r++) acc[i][j][r] = 0.f;

#pragma unroll
    for (int s = 0; s < 3; s++) {
        uint32_t base = sb + s * G_STAGE;
        int k0 = s * 32;
#pragma unroll
        for (int it = 0; it < 2; it++) cpa16(base + a_dst[it], a_src[it] + k0);
#pragma unroll
        for (int it = 0; it < 4; it++) cpa16(base + b_dst[it], b_src[it] + k0);
        CP_COMMIT();
    }

    for (int c = 0; c < KC; c++) {
        CP_WAIT(2);
        __syncthreads();
        if (c + 3 < KC) {
            uint32_t base = sb + ((c + 3) & 3) * G_STAGE;
            int k0 = (c + 3) * 32;
#pragma unroll
            for (int it = 0; it < 2; it++) cpa16(base + a_dst[it], a_src[it] + k0);
#pragma unroll
            for (int it = 0; it < 4; it++) cpa16(base + b_dst[it], b_src[it] + k0);
        }
        CP_COMMIT();

        const uint32_t abase = sb + (c & 3) * G_STAGE;
        const uint32_t bbase = abase + 8192;
#pragma unroll
        for (int ks = 0; ks < 2; ks++) {
            unsigned afr[4][4], bfr[8][2];
            uint32_t aoff = abase + a_ro + ((((ks * 2 + a_ch) ^ a_x) & 3) << 4);
#pragma unroll
            for (int i = 0; i < 4; i++) ldsm4(afr[i], aoff + i * 1024);
            uint32_t boff = bbase + b_ro + ((((ks * 2 + b_ch) ^ b_x) & 3) << 4);
#pragma unroll
            for (int jp = 0; jp < 4; jp++) {
                unsigned tmp[4];
                ldsm4(tmp, boff + jp * 1024);
                bfr[2*jp][0] = tmp[0]; bfr[2*jp][1] = tmp[1];
                bfr[2*jp+1][0] = tmp[2]; bfr[2*jp+1][1] = tmp[3];
            }
#pragma unroll
            for (int i = 0; i < 4; i++)
#pragma unroll
                for (int j = 0; j < 8; j++)
                    mma_f16(acc[i][j], afr[i], bfr[j]);
        }
    }
    CP_WAIT(0);
    __syncthreads();

    // ---- epilogue
    float Rr[8], MR[8];
    if (MODE != 2) {
#pragma unroll
        for (int i = 0; i < 4; i++)
#pragma unroll
            for (int half = 0; half < 2; half++) {
                int r = m0 + wm * 64 + i * 16 + g + half * 8;
                float rv = rs[r];
                Rr[i * 2 + half] = rv;
                MR[i * 2 + half] = mu[r] * rv;
            }
    }
    float vbv[16], vgv[16];
    if (MODE != 2) {
#pragma unroll
        for (int j = 0; j < 8; j++) {
            int cg = n0 + wn * 64 + j * 8 + 2 * t;
            vbv[2*j] = vb[cg]; vbv[2*j+1] = vb[cg+1];
            vgv[2*j] = vg[cg]; vgv[2*j+1] = vg[cg+1];
        }
    }

    const bool vpart = (MODE == 0) && (n0 >= 1024);
    __half* st = (__half*)sm;
    __half* Kb = (__half*)g_Kb4;
    __half* Qb = (__half*)g_Qb4;
    __half* Vt = (__half*)g_Vt4;

#pragma unroll
    for (int i = 0; i < 4; i++) {
#pragma unroll
        for (int j = 0; j < 8; j++) {
#pragma unroll
            for (int half = 0; half < 2; half++) {
                int rl = wm * 64 + i * 16 + g + half * 8;
                int r = m0 + rl;
                int cl = wn * 64 + j * 8 + 2 * t;
                int cg = n0 + cl;
                float v0 = acc[i][j][half * 2 + 0];
                float v1 = acc[i][j][half * 2 + 1];
                if (MODE != 2) {
                    float R = Rr[i * 2 + half], M = MR[i * 2 + half];
                    v0 = R * v0 + vbv[2*j]   - M * vgv[2*j];
                    v1 = R * v1 + vbv[2*j+1] - M * vgv[2*j+1];
                }
                if (MODE == 0) {
                    if (!vpart) {
                        int h = cg >> 7, d = cg & 127;
                        int bb2 = r >> 14, l = r & 16383;
                        unsigned u = pack2h(v0, v1);
                        *(unsigned*)(Kb + ((((size_t)(bb2 * 8 + h)) << 14) + l) * 128 + d) = u;
                    } else {
                        st[cl * 136 + rl]       = __float2half_rn(v0);
                        st[(cl + 1) * 136 + rl] = __float2half_rn(v1);
                    }
                } else if (MODE == 1) {
                    int h = cg >> 7, d = cg & 127;
                    int bb2 = r >> 9, q = r & 511;
                    unsigned u = pack2h(QSCALE * v0, QSCALE * v1);
                    *(unsigned*)(Qb + (((size_t)(bb2 * 8 + h)) * 512 + q) * 128 + d) = u;
                } else {
                    *(float2*)(C + (size_t)r * 1024 + cg) = make_float2(v0, v1);
                }
            }
        }
    }
    if (vpart) {
        __syncthreads();
        int bb2 = m0 >> 14, l0 = m0 & 16383;
#pragma unroll
        for (int cl2 = 0; cl2 < 32; cl2++) {
            int c = wid * 32 + cl2;
            int cg = n0 + c - 1024;
            int h = cg >> 7, d = cg & 127;
            uint2 v = *(const uint2*)&st[c * 136 + lane * 4];
            *(uint2*)(Vt + ((size_t)(bb2 * 8 + h) * 128 + d) * LKV + l0 + lane * 4) = v;
        }
    }
}

// ---------------------------------------------------------------------------
// FP16 flash attention. Br=128, Bc=128, 256 threads, m16n8k16, cp.async
// 2-stage, ldmatrix loads (Q re-loaded per chunk -- register-pressure-friendly).
//   S:  warps 4x2 (q32 x l64);  PV: warps 2x4 (q64 x d32).
// Smem: Q 32KB | stage0 K32+V32 | stage1 K32+V32 | P 32KB (ls overlays P).
// ---------------------------------------------------------------------------
#define AT_Q     0
#define AT_STG   32768
#define AT_P     163840
#define A_SMEM_BYTES 196608

__global__ __launch_bounds__(256, 1)
void attn_h(const __half* __restrict__ Qb, const __half* __restrict__ Kb,
            const __half* __restrict__ Vt, __half* __restrict__ AO)
{
    extern __shared__ char sm[];
    const uint32_t sb = smem_u32(sm);
    const int tid = threadIdx.x;
    const int lane = tid & 31, wid = tid >> 5;
    const int g = lane >> 2, t = lane & 3;
    const int bh = blockIdx.y;
    const int q0 = blockIdx.x * 128;

    const int wq4 = wid & 3, wl = wid >> 2;   // S phase: q 32, l 64
    const int wq2 = wid & 1, wd = wid >> 1;   // PV phase: q 64, d 32

    const __half* Qg = Qb + ((size_t)bh * LQ + q0) * DH;
    const __half* Kg = Kb + (size_t)bh * LKV * DH;
    const __half* Vg = Vt + (size_t)bh * DH * LKV;

    unsigned* Ps = (unsigned*)(sm + AT_P);

    // ldmatrix per-lane geometry
    const int ar = ((lane >> 3) & 1) * 8 + (lane & 7);
    const int ach = lane >> 4;
    const int br = ((lane >> 4) & 1) * 8 + (lane & 7);
    const int bch = (lane >> 3) & 1;
    const uint32_t q_ro = sb + AT_Q + (uint32_t)(wq4 * 32 + ar) * 256;
    const uint32_t p_ro = sb + AT_P + (uint32_t)(wq2 * 64 + ar) * 256;

    // staging assignments
    const __half* k_src[8]; uint32_t k_dst[8];
    const __half* v_src[8]; uint32_t v_dst[8];
#pragma unroll
    for (int it = 0; it < 8; it++) {
        int idx = tid + it * 256, row = idx >> 4, blk = idx & 15;
        uint32_t sw = (row * 64 + (((blk ^ row) & 15) << 2)) * 4;
        k_src[it] = Kg + (size_t)row * 128 + blk * 8;
        k_dst[it] = sw;
        v_src[it] = Vg + (size_t)row * LKV + blk * 8;
        v_dst[it] = 32768 + sw;
    }

    // prologue: Q + chunk0 (group 0), chunk1 (group 1)
#pragma unroll
    for (int it = 0; it < 8; it++) {
        int idx = tid + it * 256, row = idx >> 4, blk = idx & 15;
        cpa16(sb + AT_Q + (row * 64 + (((blk ^ row) & 15) << 2)) * 4,
              Qg + (size_t)row * 128 + blk * 8);
    }
    {
        uint32_t base = sb + AT_STG;
#pragma unroll
        for (int it = 0; it < 8; it++) cpa16(base + k_dst[it], k_src[it]);
#pragma unroll
        for (int it = 0; it < 8; it++) cpa16(base + v_dst[it], v_src[it]);
        CP_COMMIT();
    }
    {
        uint32_t base = sb + AT_STG + 65536;
#pragma unroll
        for (int it = 0; it < 8; it++) cpa16(base + k_dst[it], k_src[it] + (size_t)128 * 128);
#pragma unroll
        for (int it = 0; it < 8; it++) cpa16(base + v_dst[it], v_src[it] + 128);
        CP_COMMIT();
    }

    float oacc[4][4][4];
#pragma unroll
    for (int i = 0; i < 4; i++)
#pragma unroll
        for (int j = 0; j < 4; j++)
#pragma unroll
            for (int r = 0; r < 4; r++) oacc[i][j][r] = 0.f;
    float rsum[2][2] = {{0.f, 0.f}, {0.f, 0.f}};

    const int NC = LKV / 128;
    for (int ci = 0; ci < NC; ci++) {
        CP_WAIT(1);
        __syncthreads();
        const uint32_t stg = sb + AT_STG + (ci & 1) * 65536;
        const uint32_t k_ro = stg + (uint32_t)(wl * 64 + br) * 256;
        const uint32_t v_ro = stg + 32768 + (uint32_t)(wd * 32 + br) * 256;

        // ---- S = Q K^T : warp 32q x 64l
        float sac[2][8][4];
#pragma unroll
        for (int i = 0; i < 2; i++)
#pragma unroll
            for (int j = 0; j < 8; j++)
#pragma unroll
                for (int r = 0; r < 4; r++) sac[i][j][r] = 0.f;
#pragma unroll
        for (int ks = 0; ks < 8; ks++) {
            unsigned afr[2][4], bfr[8][2];
            uint32_t qa = q_ro + ((((ks * 2 + ach) ^ ar) & 15) << 4);
#pragma unroll
            for (int i = 0; i < 2; i++) ldsm4(afr[i], qa + i * 4096);
            uint32_t ka = k_ro + ((((ks * 2 + bch) ^ br) & 15) << 4);
#pragma unroll
            for (int jp = 0; jp < 4; jp++) {
                unsigned tmp[4];
                ldsm4(tmp, ka + jp * 4096);
                bfr[2*jp][0] = tmp[0]; bfr[2*jp][1] = tmp[1];
                bfr[2*jp+1][0] = tmp[2]; bfr[2*jp+1][1] = tmp[3];
            }
#pragma unroll
            for (int i = 0; i < 2; i++)
#pragma unroll
                for (int j = 0; j < 8; j++)
                    mma_f16(sac[i][j], afr[i], bfr[j]);
        }

        // ---- P = exp2(S), row sums, store P (half2 words, swQ64)
#pragma unroll
        for (int i = 0; i < 2; i++) {
            int r0 = wq4 * 32 + i * 16 + g;
#pragma unroll
            for (int j = 0; j < 8; j++) {
                int w = wl * 32 + j * 4 + t;
                float p0 = ex2(sac[i][j][0]);
                float p1 = ex2(sac[i][j][1]);
                float p2 = ex2(sac[i][j][2]);
                float p3 = ex2(sac[i][j][3]);
                rsum[i][0] += p0 + p1;
                rsum[i][1] += p2 + p3;
                Ps[swQ64(r0,     w)] = pack2h(p0, p1);
                Ps[swQ64(r0 + 8, w)] = pack2h(p2, p3);
            }
        }
        __syncthreads();

        // ---- O += P V : warp 64q x 32d
#pragma unroll
        for (int ks = 0; ks < 8; ks++) {
            unsigned afr[4][4], bfr[4][2];
            uint32_t pa = p_ro + ((((ks * 2 + ach) ^ ar) & 15) << 4);
#pragma unroll
            for (int i = 0; i < 4; i++) ldsm4(afr[i], pa + i * 4096);
            uint32_t va = v_ro + ((((ks * 2 + bch) ^ br) & 15) << 4);
#pragma unroll
            for (int jp = 0; jp < 2; jp++) {
                unsigned tmp[4];
                ldsm4(tmp, va + jp * 4096);
                bfr[2*jp][0] = tmp[0]; bfr[2*jp][1] = tmp[1];
                bfr[2*jp+1][0] = tmp[2]; bfr[2*jp+1][1] = tmp[3];
            }
#pragma unroll
            for (int i = 0; i < 4; i++)
#pragma unroll
                for (int j = 0; j < 4; j++)
                    mma_f16(oacc[i][j], afr[i], bfr[j]);
        }
        __syncthreads();

        if (ci + 2 < NC) {
            uint32_t base = sb + AT_STG + (ci & 1) * 65536;
            size_t koff = (size_t)(ci + 2) * 128 * 128;
            int voff = (ci + 2) * 128;
#pragma unroll
            for (int it = 0; it < 8; it++) cpa16(base + k_dst[it], k_src[it] + koff);
#pragma unroll
            for (int it = 0; it < 8; it++) cpa16(base + v_dst[it], v_src[it] + voff);
        }
        CP_COMMIT();
    }

    // ---- row-sum reduction (ls overlays P region)
    float* ls = (float*)Ps;
#pragma unroll
    for (int i = 0; i < 2; i++)
#pragma unroll
        for (int h = 0; h < 2; h++) {
            float v = rsum[i][h];
            v += __shfl_xor_sync(0xffffffffu, v, 1);
            v += __shfl_xor_sync(0xffffffffu, v, 2);
            rsum[i][h] = v;
        }
    if (t == 0) {
#pragma unroll
        for (int i = 0; i < 2; i++) {
            int r = wq4 * 32 + i * 16 + g;
            ls[wl * 128 + r]     = rsum[i][0];
            ls[wl * 128 + r + 8] = rsum[i][1];
        }
    }
    __syncthreads();

    // ---- epilogue: normalize, scatter (half2)
    int bb2 = bh >> 3, h = bh & 7;
#pragma unroll
    for (int i = 0; i < 4; i++) {
#pragma unroll
        for (int half = 0; half < 2; half++) {
            int r = wq2 * 64 + i * 16 + g + half * 8;
            float inv = 1.f / (ls[r] + ls[128 + r]);
            size_t rowoff = ((size_t)(bb2 * 512 + q0 + r)) * 1024 + h * 128;
#pragma unroll
            for (int j = 0; j < 4; j++) {
                int cc = wd * 32 + j * 8 + 2 * t;
                *(unsigned*)(AO + rowoff + cc) =
                    pack2h(oacc[i][j][half * 2] * inv, oacc[i][j][half * 2 + 1] * inv);
            }
        }
    }
}

// ---------------------------------------------------------------------------
// Launcher.
// ---------------------------------------------------------------------------
extern "C" void kernel_launch(void* const* d_in, const int* in_sizes, int n_in,
                              void* d_out, int out_size)
{
    (void)in_sizes; (void)n_in; (void)out_size;
    const float* latent   = (const float*)d_in[0];
    const float* inpkv    = (const float*)d_in[1];
    const float* W_Q      = (const float*)d_in[2];
    const float* W_K      = (const float*)d_in[3];
    const float* W_V      = (const float*)d_in[4];
    const float* W_O      = (const float*)d_in[5];
    const float* ln_lat_g = (const float*)d_in[6];
    const float* ln_lat_b = (const float*)d_in[7];
    const float* ln_in_g  = (const float*)d_in[8];
    const float* ln_in_b  = (const float*)d_in[9];
    float* out = (float*)d_out;

    float *p_mukv, *p_rskv, *p_muq, *p_rsq, *p_vb, *p_vg, *p_vbq, *p_vgq, *p_vbp, *p_vgp;
    void *p_Xkv, *p_Xq, *p_Q, *p_K, *p_Vt, *p_AO, *p_WTkv, *p_WTq, *p_WTo;
    cudaGetSymbolAddress((void**)&p_mukv, g_mu_kv);
    cudaGetSymbolAddress((void**)&p_rskv, g_rs_kv);
    cudaGetSymbolAddress((void**)&p_muq,  g_mu_q);
    cudaGetSymbolAddress((void**)&p_rsq,  g_rs_q);
    cudaGetSymbolAddress(&p_Xkv,  g_Xkv4);
    cudaGetSymbolAddress(&p_Xq,   g_Xq4);
    cudaGetSymbolAddress(&p_Q,    g_Qb4);
    cudaGetSymbolAddress(&p_K,    g_Kb4);
    cudaGetSymbolAddress(&p_Vt,   g_Vt4);
    cudaGetSymbolAddress(&p_AO,   g_AO4);
    cudaGetSymbolAddress(&p_WTkv, g_WTkv4);
    cudaGetSymbolAddress(&p_WTq,  g_WTq4);
    cudaGetSymbolAddress(&p_WTo,  g_WTo4);
    cudaGetSymbolAddress((void**)&p_vb,  g_vb);
    cudaGetSymbolAddress((void**)&p_vg,  g_vg);
    cudaGetSymbolAddress((void**)&p_vbq, g_vbq);
    cudaGetSymbolAddress((void**)&p_vgq, g_vgq);
    cudaGetSymbolAddress((void**)&p_vbp, g_vbp);
    cudaGetSymbolAddress((void**)&p_vgp, g_vgp);

    cudaFuncSetAttribute(gemm_h<0>, cudaFuncAttributeMaxDynamicSharedMemorySize, G_SMEM);
    cudaFuncSetAttribute(gemm_h<1>, cudaFuncAttributeMaxDynamicSharedMemorySize, G_SMEM);
    cudaFuncSetAttribute(gemm_h<2>, cudaFuncAttributeMaxDynamicSharedMemorySize, G_SMEM);
    cudaFuncSetAttribute(attn_h,    cudaFuncAttributeMaxDynamicSharedMemorySize, A_SMEM_BYTES);

    dim3 tb(32, 8);
    // 0: KV row stats + half copy
    rowstats_kernel<<<MKV / 8, 256>>>(inpkv, (__half*)p_Xkv, p_mukv, p_rskv, CH_IN);
    // 1,2: K|V weight transposes (gamma folded)
    wtrans_kernel<<<dim3(32, 24), tb>>>(W_K, (__half*)p_WTkv,              768, 1024, ln_in_g);
    wtrans_kernel<<<dim3(32, 24), tb>>>(W_V, (__half*)p_WTkv + 1024 * 768, 768, 1024, ln_in_g);
    // 3,4: LN fold vectors for K|V (split-K + reduce)
    vbvg_part<<<dim3(32, 6), 256>>>(W_K, W_V, ln_in_g, ln_in_b, p_vbp, p_vgp, 2048);
    vbvg_reduce<<<8, 256>>>(p_vbp, p_vgp, p_vb, p_vg, 6, 2048);
    // 5: K|V projection (single launch)
    gemm_h<0><<<dim3(8, 1024), 256, G_SMEM>>>((const __half*)p_Xkv, (const __half*)p_WTkv,
                                              p_mukv, p_rskv, p_vb, p_vg, nullptr, CH_IN);
    // 6: Q row stats + half copy
    rowstats_kernel<<<MQ / 8, 256>>>(latent, (__half*)p_Xq, p_muq, p_rsq, CH_LAT);
    // 7-9: Q weight prep
    wtrans_kernel<<<dim3(32, 32), tb>>>(W_Q, (__half*)p_WTq, 1024, 1024, ln_lat_g);
    vbvg_part<<<dim3(16, 8), 256>>>(W_Q, W_Q, ln_lat_g, ln_lat_b, p_vbp, p_vgp, 1024);
    vbvg_reduce<<<4, 256>>>(p_vbp, p_vgp, p_vbq, p_vgq, 8, 1024);
    // 10: Q projection
    gemm_h<1><<<dim3(4, 32), 256, G_SMEM>>>((const __half*)p_Xq, (const __half*)p_WTq,
                                            p_muq, p_rsq, p_vbq, p_vgq, nullptr, CH_LAT);
    // 11: flash attention
    attn_h<<<dim3(4, BH), 256, A_SMEM_BYTES>>>((const __half*)p_Q, (const __half*)p_K,
                                               (const __half*)p_Vt, (__half*)p_AO);
    // 12: O weight transpose
    wtrans_kernel<<<dim3(32, 32), tb>>>(W_O, (__half*)p_WTo, 1024, 1024, nullptr);
    // 13: output projection (float out)
    gemm_h<2><<<dim3(4, 32), 256, G_SMEM>>>((const __half*)p_AO, (const __half*)p_WTo,
                                            nullptr, nullptr, nullptr, nullptr, out, 1024);
}

// round 15
// speedup vs baseline: 1.1176x; 1.0515x over previous
#include <cuda_runtime.h>
#include <cuda_fp16.h>
#include <math.h>
#include <stdint.h>

// ---------------------------------------------------------------------------
// Problem dims
// ---------------------------------------------------------------------------
#define NB      8
#define LQ      512
#define LKV     16384
#define CH_LAT  1024
#define CH_IN   768
#define DH      128
#define NH      8
#define BH      (NB*NH)        // 64
#define MKV     (NB*LKV)       // 131072
#define MQ      (NB*LQ)        // 4096

// 1/sqrt(128) * log2(e)  (folded into Q; softmax uses exp2)
#define QSCALE  (0.08838834764831845f * 1.4426950408889634f)

// ---------------------------------------------------------------------------
// Scratch (device globals; uint4-typed for 16B alignment, cast to __half)
// ---------------------------------------------------------------------------
__device__ float g_mu_kv[MKV], g_rs_kv[MKV];
__device__ float g_mu_q[MQ],   g_rs_q[MQ];
__device__ uint4 g_Xkv4[(size_t)MKV*CH_IN/8];    // half copy of input_kv
__device__ uint4 g_Xq4 [(size_t)MQ*CH_LAT/8];    // half copy of latent
__device__ uint4 g_Qb4 [(size_t)BH*LQ*DH/8];     // half [bh][q][d], QSCALE folded
__device__ uint4 g_Kb4 [(size_t)BH*LKV*DH/8];    // half [bh][l][d]
__device__ uint4 g_Vt4 [(size_t)BH*DH*LKV/8];    // half [bh][d][l]
__device__ uint4 g_AO4 [(size_t)MQ*1024/8];      // half [b*512+q][h*128+d]
__device__ uint4 g_WTkv4[2048*768/8];            // half (gamma*W)^T; <1024: K, >=1024: V
__device__ uint4 g_WTq4 [1024*1024/8];
__device__ uint4 g_WTo4 [1024*1024/8];
__device__ float g_vb[2048], g_vg[2048];         // beta^T W, gamma^T W (KV)
__device__ float g_vbq[1024], g_vgq[1024];       // (Q)
__device__ float g_vbp[8*2048], g_vgp[8*2048];   // split-K partials
__device__ unsigned g_vcnt = 0;                  // completion ticket (self-resetting)

// ---------------------------------------------------------------------------
// helpers
// ---------------------------------------------------------------------------
__device__ __forceinline__ float ex2(float x) {
    float y; asm("ex2.approx.ftz.f32 %0, %1;" : "=f"(y) : "f"(x)); return y;
}
__device__ __forceinline__ unsigned pack2h(float a, float b) {
    __half2 h = __floats2half2_rn(a, b);
    return *(unsigned*)&h;
}
__device__ __forceinline__ uint32_t smem_u32(const void* p) {
    uint32_t a;
    asm("{ .reg .u64 t; cvta.to.shared.u64 t, %1; cvt.u32.u64 %0, t; }" : "=r"(a) : "l"(p));
    return a;
}
__device__ __forceinline__ void cpa16(uint32_t dst, const void* src) {
    asm volatile("cp.async.cg.shared.global [%0], [%1], 16;" :: "r"(dst), "l"(src));
}
#define CP_COMMIT() asm volatile("cp.async.commit_group;")
#define CP_WAIT(N)  asm volatile("cp.async.wait_group %0;" :: "n"(N))

__device__ __forceinline__ void mma_f16(float* c, const unsigned* a, const unsigned* b) {
    asm volatile(
        "mma.sync.aligned.m16n8k16.row.col.f32.f16.f16.f32 "
        "{%0,%1,%2,%3}, {%4,%5,%6,%7}, {%8,%9}, {%0,%1,%2,%3};\n"
        : "+f"(c[0]), "+f"(c[1]), "+f"(c[2]), "+f"(c[3])
        : "r"(a[0]), "r"(a[1]), "r"(a[2]), "r"(a[3]), "r"(b[0]), "r"(b[1]));
}
__device__ __forceinline__ void ldsm4(unsigned* r, uint32_t a) {
    asm volatile("ldmatrix.sync.aligned.m8n8.x4.shared.b16 {%0,%1,%2,%3}, [%4];"
                 : "=r"(r[0]), "=r"(r[1]), "=r"(r[2]), "=r"(r[3]) : "r"(a));
}

// Swizzled word (b32 = half2) offsets
__device__ __forceinline__ int swQ64(int row, int w) {   // 64-word (128-half) rows
    return row * 64 + ((((w >> 2) ^ row) & 15) << 2) + (w & 3);
}

// ---------------------------------------------------------------------------
// Row stats + half copy (one warp per row)
// ---------------------------------------------------------------------------
__global__ void rowstats_kernel(const float* __restrict__ X, __half* __restrict__ Xh,
                                float* __restrict__ mu, float* __restrict__ rs, int cols)
{
    int row  = blockIdx.x * 8 + (threadIdx.x >> 5);
    int lane = threadIdx.x & 31;
    const float* xr = X + (size_t)row * cols;
    __half* xo = Xh + (size_t)row * cols;
    float s = 0.f, s2 = 0.f;
    for (int c = lane; c < cols; c += 32) {
        float v = xr[c];
        xo[c] = __float2half_rn(v);
        s += v; s2 += v * v;
    }
#pragma unroll
    for (int o = 16; o; o >>= 1) {
        s  += __shfl_xor_sync(0xffffffffu, s,  o);
        s2 += __shfl_xor_sync(0xffffffffu, s2, o);
    }
    if (lane == 0) {
        float m = s / cols;
        float var = fmaxf(s2 / cols - m * m, 0.f);
        mu[row] = m; rs[row] = rsqrtf(var + 1e-5f);
    }
}

// ---------------------------------------------------------------------------
// Weight transpose: out[c][r] = half(in[r][c] * (scale?scale[r]:1))
// Single-matrix and z-merged two-matrix variants.
// ---------------------------------------------------------------------------
__global__ void wtrans_kernel(const float* __restrict__ in, __half* __restrict__ out,
                              int R, int C, const float* __restrict__ scale)
{
    __shared__ float t[32][33];
    int c0 = blockIdx.x * 32, r0 = blockIdx.y * 32;
    int tx = threadIdx.x, ty = threadIdx.y;
#pragma unroll
    for (int j = 0; j < 4; j++) {
        int r = r0 + ty + j * 8;
        float v = in[(size_t)r * C + c0 + tx];
        if (scale) v *= scale[r];
        t[ty + j * 8][tx] = v;
    }
    __syncthreads();
#pragma unroll
    for (int j = 0; j < 4; j++)
        out[(size_t)(c0 + ty + j * 8) * R + r0 + tx] = __float2half_rn(t[tx][ty + j * 8]);
}

__global__ void wtrans2_kernel(const float* __restrict__ inA, const float* __restrict__ inB,
                               __half* __restrict__ out, int R, int C,
                               const float* __restrict__ scale)
{
    __shared__ float t[32][33];
    const float* in = blockIdx.z ? inB : inA;
    __half* o = out + (size_t)blockIdx.z * C * R;
    int c0 = blockIdx.x * 32, r0 = blockIdx.y * 32;
    int tx = threadIdx.x, ty = threadIdx.y;
#pragma unroll
    for (int j = 0; j < 4; j++) {
        int r = r0 + ty + j * 8;
        float v = in[(size_t)r * C + c0 + tx] * scale[r];
        t[ty + j * 8][tx] = v;
    }
    __syncthreads();
#pragma unroll
    for (int j = 0; j < 4; j++)
        o[(size_t)(c0 + ty + j * 8) * R + r0 + tx] = __float2half_rn(t[tx][ty + j * 8]);
}

// ---------------------------------------------------------------------------
// vb/vg fold vectors: split-K partials, last block reduces (ticket counter).
// grid (N/64, S). n<1024 -> W0, else W1.
// ---------------------------------------------------------------------------
__global__ void vbvg_fused(const float* __restrict__ W0, const float* __restrict__ W1,
                           const float* __restrict__ gamma, const float* __restrict__ beta,
                           float* __restrict__ vbp, float* __restrict__ vgp,
                           float* __restrict__ vb, float* __restrict__ vg,
                           int N, int rows_per_slice)
{
    __shared__ float sbv[4][64], sgv[4][64];
    __shared__ unsigned ticket;
    int nl = threadIdx.x & 63;
    int n = blockIdx.x * 64 + nl;
    int rg = threadIdx.x >> 6;
    int r0 = blockIdx.y * rows_per_slice;
    const float* W = (n < 1024) ? W0 : W1;
    int nn = n & 1023;
    float sb = 0.f, sg = 0.f;
#pragma unroll 4
    for (int r = r0 + rg; r < r0 + rows_per_slice; r += 4) {
        float w = W[(size_t)r * 1024 + nn];
        sb += beta[r] * w;
        sg += gamma[r] * w;
    }
    sbv[rg][nl] = sb;
    sgv[rg][nl] = sg;
    __syncthreads();
    if (threadIdx.x < 64) {
        vbp[(size_t)blockIdx.y * N + n] = sbv[0][nl] + sbv[1][nl] + sbv[2][nl] + sbv[3][nl];
        vgp[(size_t)blockIdx.y * N + n] = sgv[0][nl] + sgv[1][nl] + sgv[2][nl] + sgv[3][nl];
    }
    __threadfence();
    __syncthreads();
    if (threadIdx.x == 0) ticket = atomicAdd(&g_vcnt, 1u);
    __syncthreads();
    if (ticket == gridDim.x * gridDim.y - 1) {
        int S = gridDim.y;
        for (int nn2 = (int)threadIdx.x; nn2 < N; nn2 += 256) {
            float a = 0.f, b = 0.f;
            for (int s = 0; s < S; s++) {
                a += vbp[(size_t)s * N + nn2];
                b += vgp[(size_t)s * N + nn2];
            }
            vb[nn2] = a; vg[nn2] = b;
        }
        __threadfence();
        if (threadIdx.x == 0) g_vcnt = 0;   // reset for next use / graph replay
    }
}

// ---------------------------------------------------------------------------
// FP16 GEMM: block 128x256, BK=64, 256 threads (8 warps 2x4), warp 64x64,
// m16n8k16, cp.async 3-stage (stage = A 16KB + B 32KB), ldmatrix loads.
// Rows are 64 halfs (128B, 8 x16B blocks); swizzle blk' = blk ^ (row&7).
// MODE 0: -> g_Kb half (n<1024) / g_Vt half transposed (n>=1024)
// MODE 1: -> g_Qb half, *QSCALE
// MODE 2: -> float row-major C
// ---------------------------------------------------------------------------
#define G_STAGE 49152
#define G_SMEM  (3*G_STAGE)      // 144KB

template<int MODE>
__global__ __launch_bounds__(256, 1)
void gemm_h(const __half* __restrict__ A, const __half* __restrict__ WT,
            const float* __restrict__ mu, const float* __restrict__ rs,
            const float* __restrict__ vb, const float* __restrict__ vg,
            float* __restrict__ C, int K)
{
    extern __shared__ char sm[];
    const uint32_t sb = smem_u32(sm);
    const int tid = threadIdx.x;
    const int lane = tid & 31, wid = tid >> 5;
    const int wm = wid >> 2, wn = wid & 3;
    const int g = lane >> 2, t = lane & 3;
    const int m0 = blockIdx.y * 128, n0 = blockIdx.x * 256;
    const int KC = K >> 6;

    // staging bases: task idx = tid + it*256; row = idx>>3, blk = idx&7.
    // it-stride: +32 rows -> src += 32*K halfs, dst += 4096 bytes (row&7 invariant).
    const int srow = tid >> 3, sblk = tid & 7;
    const __half* a_src0 = A  + (size_t)(m0 + srow) * K + sblk * 8;
    const __half* b_src0 = WT + (size_t)(n0 + srow) * K + sblk * 8;
    const uint32_t s_dst0 = (uint32_t)(srow * 128 + (((sblk ^ (srow & 7)) & 7) << 4));

    // ldmatrix per-lane geometry
    const int a_row = ((lane >> 3) & 1) * 8 + (lane & 7);
    const int a_ch  = lane >> 4;
    const int ax7   = a_row & 7;
    const uint32_t a_ro = (uint32_t)(wm * 64 + a_row) * 128;
    const int b_row = ((lane >> 4) & 1) * 8 + (lane & 7);
    const int b_ch  = (lane >> 3) & 1;
    const int bx7   = b_row & 7;
    const uint32_t b_ro = 16384u + (uint32_t)(wn * 64 + b_row) * 128;

    float acc[4][8][4];
#pragma unroll
    for (int i = 0; i < 4; i++)
#pragma unroll
        for (int j = 0; j < 8; j++)
#pragma unroll
            for (int r = 0; r < 4; r++) acc[i][j][r] = 0.f;

    // prologue: stages 0,1
#pragma unroll
    for (int s = 0; s < 2; s++) {
        uint32_t base = sb + s * G_STAGE;
        int k0 = s * 64;
#pragma unroll
        for (int it = 0; it < 4; it++)
            cpa16(base + s_dst0 + it * 4096, a_src0 + (size_t)it * 32 * K + k0);
#pragma unroll
        for (int it = 0; it < 8; it++)
            cpa16(base + 16384 + s_dst0 + it * 4096, b_src0 + (size_t)it * 32 * K + k0);
        CP_COMMIT();
    }

    for (int c = 0; c < KC; c++) {
        CP_WAIT(1);
        __syncthreads();
        if (c + 2 < KC) {
            uint32_t base = sb + ((c + 2) % 3) * G_STAGE;
            int k0 = (c + 2) * 64;
#pragma unroll
            for (int it = 0; it < 4; it++)
                cpa16(base + s_dst0 + it * 4096, a_src0 + (size_t)it * 32 * K + k0);
#pragma unroll
            for (int it = 0; it < 8; it++)
                cpa16(base + 16384 + s_dst0 + it * 4096, b_src0 + (size_t)it * 32 * K + k0);
        }
        CP_COMMIT();

        const uint32_t abase = sb + (c % 3) * G_STAGE;
#pragma unroll
        for (int ks = 0; ks < 4; ks++) {
            unsigned afr[4][4], bfr[8][2];
            uint32_t aoff = abase + a_ro + ((((ks * 2 + a_ch) ^ ax7) & 7) << 4);
#pragma unroll
            for (int i = 0; i < 4; i++) ldsm4(afr[i], aoff + i * 2048);
            uint32_t boff = abase + b_ro + ((((ks * 2 + b_ch) ^ bx7) & 7) << 4);
#pragma unroll
            for (int jp = 0; jp < 4; jp++) {
                unsigned tmp[4];
                ldsm4(tmp, boff + jp * 2048);
                bfr[2*jp][0] = tmp[0]; bfr[2*jp][1] = tmp[1];
                bfr[2*jp+1][0] = tmp[2]; bfr[2*jp+1][1] = tmp[3];
            }
#pragma unroll
            for (int i = 0; i < 4; i++)
#pragma unroll
                for (int j = 0; j < 8; j++)
                    mma_f16(acc[i][j], afr[i], bfr[j]);
        }
    }
    CP_WAIT(0);
    __syncthreads();

    // ---- epilogue
    float Rr[8], MR[8];
    if (MODE != 2) {
#pragma unroll
        for (int i = 0; i < 4; i++)
#pragma unroll
            for (int half = 0; half < 2; half++) {
                int r = m0 + wm * 64 + i * 16 + g + half * 8;
                float rv = rs[r];
                Rr[i * 2 + half] = rv;
                MR[i * 2 + half] = mu[r] * rv;
            }
    }
    float vbv[16], vgv[16];
    if (MODE != 2) {
#pragma unroll
        for (int j = 0; j < 8; j++) {
            int cg = n0 + wn * 64 + j * 8 + 2 * t;
            vbv[2*j] = vb[cg]; vbv[2*j+1] = vb[cg+1];
            vgv[2*j] = vg[cg]; vgv[2*j+1] = vg[cg+1];
        }
    }

    const bool vpart = (MODE == 0) && (n0 >= 1024);
    __half* st = (__half*)sm;
    __half* Kb = (__half*)g_Kb4;
    __half* Qb = (__half*)g_Qb4;
    __half* Vt = (__half*)g_Vt4;

#pragma unroll
    for (int i = 0; i < 4; i++) {
#pragma unroll
        for (int j = 0; j < 8; j++) {
#pragma unroll
            for (int half = 0; half < 2; half++) {
                int rl = wm * 64 + i * 16 + g + half * 8;
                int r = m0 + rl;
                int cl = wn * 64 + j * 8 + 2 * t;
                int cg = n0 + cl;
                float v0 = acc[i][j][half * 2 + 0];
                float v1 = acc[i][j][half * 2 + 1];
                if (MODE != 2) {
                    float R = Rr[i * 2 + half], M = MR[i * 2 + half];
                    v0 = R * v0 + vbv[2*j]   - M * vgv[2*j];
                    v1 = R * v1 + vbv[2*j+1] - M * vgv[2*j+1];
                }
                if (MODE == 0) {
                    if (!vpart) {
                        int h = cg >> 7, d = cg & 127;
                        int bb2 = r >> 14, l = r & 16383;
                        unsigned u = pack2h(v0, v1);
                        *(unsigned*)(Kb + ((((size_t)(bb2 * 8 + h)) << 14) + l) * 128 + d) = u;
                    } else {
                        st[cl * 136 + rl]       = __float2half_rn(v0);
                        st[(cl + 1) * 136 + rl] = __float2half_rn(v1);
                    }
                } else if (MODE == 1) {
                    int h = cg >> 7, d = cg & 127;
                    int bb2 = r >> 9, q = r & 511;
                    unsigned u = pack2h(QSCALE * v0, QSCALE * v1);
                    *(unsigned*)(Qb + (((size_t)(bb2 * 8 + h)) * 512 + q) * 128 + d) = u;
                } else {
                    *(float2*)(C + (size_t)r * 1024 + cg) = make_float2(v0, v1);
                }
            }
        }
    }
    if (vpart) {
        __syncthreads();
        int bb2 = m0 >> 14, l0 = m0 & 16383;
#pragma unroll
        for (int cl2 = 0; cl2 < 32; cl2++) {
            int c = wid * 32 + cl2;
            int cg = n0 + c - 1024;
            int h = cg >> 7, d = cg & 127;
            uint2 v = *(const uint2*)&st[c * 136 + lane * 4];
            *(uint2*)(Vt + ((size_t)(bb2 * 8 + h) * 128 + d) * LKV + l0 + lane * 4) = v;
        }
    }
}

// ---------------------------------------------------------------------------
// FP16 flash attention (R13-proven). Br=128, Bc=128, 256 threads, m16n8k16,
// cp.async 2-stage, ldmatrix loads (Q re-loaded per chunk).
//   S:  warps 4x2 (q32 x l64);  PV: warps 2x4 (q64 x d32).
// Smem: Q 32KB | stage0 K32+V32 | stage1 K32+V32 | P 32KB (ls overlays P).
// ---------------------------------------------------------------------------
#define AT_Q     0
#define AT_STG   32768
#define AT_P     163840
#define A_SMEM_BYTES 196608

__global__ __launch_bounds__(256, 1)
void attn_h(const __half* __restrict__ Qb, const __half* __restrict__ Kb,
            const __half* __restrict__ Vt, __half* __restrict__ AO)
{
    extern __shared__ char sm[];
    const uint32_t sb = smem_u32(sm);
    const int tid = threadIdx.x;
    const int lane = tid & 31, wid = tid >> 5;
    const int g = lane >> 2, t = lane & 3;
    const int bh = blockIdx.y;
    const int q0 = blockIdx.x * 128;

    const int wq4 = wid & 3, wl = wid >> 2;   // S phase: q 32, l 64
    const int wq2 = wid & 1, wd = wid >> 1;   // PV phase: q 64, d 32

    const __half* Qg = Qb + ((size_t)bh * LQ + q0) * DH;
    const __half* Kg = Kb + (size_t)bh * LKV * DH;
    const __half* Vg = Vt + (size_t)bh * DH * LKV;

    unsigned* Ps = (unsigned*)(sm + AT_P);

    // ldmatrix per-lane geometry
    const int ar = ((lane >> 3) & 1) * 8 + (lane & 7);
    const int ach = lane >> 4;
    const int br = ((lane >> 4) & 1) * 8 + (lane & 7);
    const int bch = (lane >> 3) & 1;
    const uint32_t q_ro = sb + AT_Q + (uint32_t)(wq4 * 32 + ar) * 256;
    const uint32_t p_ro = sb + AT_P + (uint32_t)(wq2 * 64 + ar) * 256;

    // staging assignments
    const __half* k_src[8]; uint32_t k_dst[8];
    const __half* v_src[8]; uint32_t v_dst[8];
#pragma unroll
    for (int it = 0; it < 8; it++) {
        int idx = tid + it * 256, row = idx >> 4, blk = idx & 15;
        uint32_t sw = (row * 64 + (((blk ^ row) & 15) << 2)) * 4;
        k_src[it] = Kg + (size_t)row * 128 + blk * 8;
        k_dst[it] = sw;
        v_src[it] = Vg + (size_t)row * LKV + blk * 8;
        v_dst[it] = 32768 + sw;
    }

    // prologue: Q + chunk0 (group 0), chunk1 (group 1)
#pragma unroll
    for (int it = 0; it < 8; it++) {
        int idx = tid + it * 256, row = idx >> 4, blk = idx & 15;
        cpa16(sb + AT_Q + (row * 64 + (((blk ^ row) & 15) << 2)) * 4,
              Qg + (size_t)row * 128 + blk * 8);
    }
    {
        uint32_t base = sb + AT_STG;
#pragma unroll
        for (int it = 0; it < 8; it++) cpa16(base + k_dst[it], k_src[it]);
#pragma unroll
        for (int it = 0; it < 8; it++) cpa16(base + v_dst[it], v_src[it]);
        CP_COMMIT();
    }
    {
        uint32_t base = sb + AT_STG + 65536;
#pragma unroll
        for (int it = 0; it < 8; it++) cpa16(base + k_dst[it], k_src[it] + (size_t)128 * 128);
#pragma unroll
        for (int it = 0; it < 8; it++) cpa16(base + v_dst[it], v_src[it] + 128);
        CP_COMMIT();
    }

    float oacc[4][4][4];
#pragma unroll
    for (int i = 0; i < 4; i++)
#pragma unroll
        for (int j = 0; j < 4; j++)
#pragma unroll
            for (int r = 0; r < 4; r++) oacc[i][j][r] = 0.f;
    float rsum[2][2] = {{0.f, 0.f}, {0.f, 0.f}};

    const int NC = LKV / 128;
    for (int ci = 0; ci < NC; ci++) {
        CP_WAIT(1);
        __syncthreads();
        const uint32_t stg = sb + AT_STG + (ci & 1) * 65536;
        const uint32_t k_ro = stg + (uint32_t)(wl * 64 + br) * 256;
        const uint32_t v_ro = stg + 32768 + (uint32_t)(wd * 32 + br) * 256;

        // ---- S = Q K^T : warp 32q x 64l
        float sac[2][8][4];
#pragma unroll
        for (int i = 0; i < 2; i++)
#pragma unroll
            for (int j = 0; j < 8; j++)
#pragma unroll
                for (int r = 0; r < 4; r++) sac[i][j][r] = 0.f;
#pragma unroll
        for (int ks = 0; ks < 8; ks++) {
            unsigned afr[2][4], bfr[8][2];
            uint32_t qa = q_ro + ((((ks * 2 + ach) ^ ar) & 15) << 4);
#pragma unroll
            for (int i = 0; i < 2; i++) ldsm4(afr[i], qa + i * 4096);
            uint32_t ka = k_ro + ((((ks * 2 + bch) ^ br) & 15) << 4);
#pragma unroll
            for (int jp = 0; jp < 4; jp++) {
                unsigned tmp[4];
                ldsm4(tmp, ka + jp * 4096);
                bfr[2*jp][0] = tmp[0]; bfr[2*jp][1] = tmp[1];
                bfr[2*jp+1][0] = tmp[2]; bfr[2*jp+1][1] = tmp[3];
            }
#pragma unroll
            for (int i = 0; i < 2; i++)
#pragma unroll
                for (int j = 0; j < 8; j++)
                    mma_f16(sac[i][j], afr[i], bfr[j]);
        }

        // ---- P = exp2(S), row sums, store P (half2 words, swQ64)
#pragma unroll
        for (int i = 0; i < 2; i++) {
            int r0 = wq4 * 32 + i * 16 + g;
#pragma unroll
            for (int j = 0; j < 8; j++) {
                int w = wl * 32 + j * 4 + t;
                float p0 = ex2(sac[i][j][0]);
                float p1 = ex2(sac[i][j][1]);
                float p2 = ex2(sac[i][j][2]);
                float p3 = ex2(sac[i][j][3]);
                rsum[i][0] += p0 + p1;
                rsum[i][1] += p2 + p3;
                Ps[swQ64(r0,     w)] = pack2h(p0, p1);
                Ps[swQ64(r0 + 8, w)] = pack2h(p2, p3);
            }
        }
        __syncthreads();

        // ---- O += P V : warp 64q x 32d
#pragma unroll
        for (int ks = 0; ks < 8; ks++) {
            unsigned afr[4][4], bfr[4][2];
            uint32_t pa = p_ro + ((((ks * 2 + ach) ^ ar) & 15) << 4);
#pragma unroll
            for (int i = 0; i < 4; i++) ldsm4(afr[i], pa + i * 4096);
            uint32_t va = v_ro + ((((ks * 2 + bch) ^ br) & 15) << 4);
#pragma unroll
            for (int jp = 0; jp < 2; jp++) {
                unsigned tmp[4];
                ldsm4(tmp, va + jp * 4096);
                bfr[2*jp][0] = tmp[0]; bfr[2*jp][1] = tmp[1];
                bfr[2*jp+1][0] = tmp[2]; bfr[2*jp+1][1] = tmp[3];
            }
#pragma unroll
            for (int i = 0; i < 4; i++)
#pragma unroll
                for (int j = 0; j < 4; j++)
                    mma_f16(oacc[i][j], afr[i], bfr[j]);
        }
        __syncthreads();

        if (ci + 2 < NC) {
            uint32_t base = sb + AT_STG + (ci & 1) * 65536;
            size_t koff = (size_t)(ci + 2) * 128 * 128;
            int voff = (ci + 2) * 128;
#pragma unroll
            for (int it = 0; it < 8; it++) cpa16(base + k_dst[it], k_src[it] + koff);
#pragma unroll
            for (int it = 0; it < 8; it++) cpa16(base + v_dst[it], v_src[it] + voff);
        }
        CP_COMMIT();
    }

    // ---- row-sum reduction (ls overlays P region)
    float* ls = (float*)Ps;
#pragma unroll
    for (int i = 0; i < 2; i++)
#pragma unroll
        for (int h = 0; h < 2; h++) {
            float v = rsum[i][h];
            v += __shfl_xor_sync(0xffffffffu, v, 1);
            v += __shfl_xor_sync(0xffffffffu, v, 2);
            rsum[i][h] = v;
        }
    if (t == 0) {
#pragma unroll
        for (int i = 0; i < 2; i++) {
            int r = wq4 * 32 + i * 16 + g;
            ls[wl * 128 + r]     = rsum[i][0];
            ls[wl * 128 + r + 8] = rsum[i][1];
        }
    }
    __syncthreads();

    // ---- epilogue: normalize, scatter (half2)
    int bb2 = bh >> 3, h = bh & 7;
#pragma unroll
    for (int i = 0; i < 4; i++) {
#pragma unroll
        for (int half = 0; half < 2; half++) {
            int r = wq2 * 64 + i * 16 + g + half * 8;
            float inv = 1.f / (ls[r] + ls[128 + r]);
            size_t rowoff = ((size_t)(bb2 * 512 + q0 + r)) * 1024 + h * 128;
#pragma unroll
            for (int j = 0; j < 4; j++) {
                int cc = wd * 32 + j * 8 + 2 * t;
                *(unsigned*)(AO + rowoff + cc) =
                    pack2h(oacc[i][j][half * 2] * inv, oacc[i][j][half * 2 + 1] * inv);
            }
        }
    }
}

// ---------------------------------------------------------------------------
// Launcher. gemm_h<0> is OUR launch index 3 (harness prepends 2 -> ncu -s 5
// lands on it).
// ---------------------------------------------------------------------------
extern "C" void kernel_launch(void* const* d_in, const int* in_sizes, int n_in,
                              void* d_out, int out_size)
{
    (void)in_sizes; (void)n_in; (void)out_size;
    const float* latent   = (const float*)d_in[0];
    const float* inpkv    = (const float*)d_in[1];
    const float* W_Q      = (const float*)d_in[2];
    const float* W_K      = (const float*)d_in[3];
    const float* W_V      = (const float*)d_in[4];
    const float* W_O      = (const float*)d_in[5];
    const float* ln_lat_g = (const float*)d_in[6];
    const float* ln_lat_b = (const float*)d_in[7];
    const float* ln_in_g  = (const float*)d_in[8];
    const float* ln_in_b  = (const float*)d_in[9];
    float* out = (float*)d_out;

    float *p_mukv, *p_rskv, *p_muq, *p_rsq, *p_vb, *p_vg, *p_vbq, *p_vgq, *p_vbp, *p_vgp;
    void *p_Xkv, *p_Xq, *p_Q, *p_K, *p_Vt, *p_AO, *p_WTkv, *p_WTq, *p_WTo;
    cudaGetSymbolAddress((void**)&p_mukv, g_mu_kv);
    cudaGetSymbolAddress((void**)&p_rskv, g_rs_kv);
    cudaGetSymbolAddress((void**)&p_muq,  g_mu_q);
    cudaGetSymbolAddress((void**)&p_rsq,  g_rs_q);
    cudaGetSymbolAddress(&p_Xkv,  g_Xkv4);
    cudaGetSymbolAddress(&p_Xq,   g_Xq4);
    cudaGetSymbolAddress(&p_Q,    g_Qb4);
    cudaGetSymbolAddress(&p_K,    g_Kb4);
    cudaGetSymbolAddress(&p_Vt,   g_Vt4);
    cudaGetSymbolAddress(&p_AO,   g_AO4);
    cudaGetSymbolAddress(&p_WTkv, g_WTkv4);
    cudaGetSymbolAddress(&p_WTq,  g_WTq4);
    cudaGetSymbolAddress(&p_WTo,  g_WTo4);
    cudaGetSymbolAddress((void**)&p_vb,  g_vb);
    cudaGetSymbolAddress((void**)&p_vg,  g_vg);
    cudaGetSymbolAddress((void**)&p_vbq, g_vbq);
    cudaGetSymbolAddress((void**)&p_vgq, g_vgq);
    cudaGetSymbolAddress((void**)&p_vbp, g_vbp);
    cudaGetSymbolAddress((void**)&p_vgp, g_vgp);

    cudaFuncSetAttribute(gemm_h<0>, cudaFuncAttributeMaxDynamicSharedMemorySize, G_SMEM);
    cudaFuncSetAttribute(gemm_h<1>, cudaFuncAttributeMaxDynamicSharedMemorySize, G_SMEM);
    cudaFuncSetAttribute(gemm_h<2>, cudaFuncAttributeMaxDynamicSharedMemorySize, G_SMEM);
    cudaFuncSetAttribute(attn_h,    cudaFuncAttributeMaxDynamicSharedMemorySize, A_SMEM_BYTES);

    dim3 tb(32, 8);
    // 0: KV row stats + half copy
    rowstats_kernel<<<MKV / 8, 256>>>(inpkv, (__half*)p_Xkv, p_mukv, p_rskv, CH_IN);
    // 1: K|V weight transposes (z-merged, gamma folded)
    wtrans2_kernel<<<dim3(32, 24, 2), tb>>>(W_K, W_V, (__half*)p_WTkv, 768, 1024, ln_in_g);
    // 2: LN fold vectors for K|V (split-K + last-block reduce, one launch)
    vbvg_fused<<<dim3(32, 6), 256>>>(W_K, W_V, ln_in_g, ln_in_b,
                                     p_vbp, p_vgp, p_vb, p_vg, 2048, 128);
    // 3: K|V projection  <-- profiled (ncu -s 5)
    gemm_h<0><<<dim3(8, 1024), 256, G_SMEM>>>((const __half*)p_Xkv, (const __half*)p_WTkv,
                                              p_mukv, p_rskv, p_vb, p_vg, nullptr, CH_IN);
    // 4: Q row stats + half copy
    rowstats_kernel<<<MQ / 8, 256>>>(latent, (__half*)p_Xq, p_muq, p_rsq, CH_LAT);
    // 5,6: Q weight prep
    wtrans_kernel<<<dim3(32, 32), tb>>>(W_Q, (__half*)p_WTq, 1024, 1024, ln_lat_g);
    vbvg_fused<<<dim3(16, 8), 256>>>(W_Q, W_Q, ln_lat_g, ln_lat_b,
                                     p_vbp, p_vgp, p_vbq, p_vgq, 1024, 128);
    // 7: Q projection
    gemm_h<1><<<dim3(4, 32), 256, G_SMEM>>>((const __half*)p_Xq, (const __half*)p_WTq,
                                            p_muq, p_rsq, p_vbq, p_vgq, nullptr, CH_LAT);
    // 8: flash attention
    attn_h<<<dim3(4, BH), 256, A_SMEM_BYTES>>>((const __half*)p_Q, (const __half*)p_K,
                                               (const __half*)p_Vt, (__half*)p_AO);
    // 9: O weight transpose
    wtrans_kernel<<<dim3(32, 32), tb>>>(W_O, (__half*)p_WTo, 1024, 1024, nullptr);
    // 10: output projection (float out)
    gemm_h<2><<<dim3(4, 32), 256, G_SMEM>>>((const __half*)p_AO, (const __half*)p_WTo,
                                            nullptr, nullptr, nullptr, nullptr, out, 1024);
}

// round 17
// speedup vs baseline: 1.1317x; 1.0126x over previous
#include <cuda_runtime.h>
#include <cuda_fp16.h>
#include <math.h>
#include <stdint.h>

// ---------------------------------------------------------------------------
// Problem dims
// ---------------------------------------------------------------------------
#define NB      8
#define LQ      512
#define LKV     16384
#define CH_LAT  1024
#define CH_IN   768
#define DH      128
#define NH      8
#define BH      (NB*NH)        // 64
#define MKV     (NB*LKV)       // 131072
#define MQ      (NB*LQ)        // 4096

// 1/sqrt(128) * log2(e)  (folded into Q; softmax uses exp2)
#define QSCALE  (0.08838834764831845f * 1.4426950408889634f)

// ---------------------------------------------------------------------------
// Scratch (device globals; uint4-typed for 16B alignment, cast to __half)
// ---------------------------------------------------------------------------
__device__ float g_mu_kv[MKV], g_rs_kv[MKV];
__device__ float g_mu_q[MQ],   g_rs_q[MQ];
__device__ uint4 g_Xkv4[(size_t)MKV*CH_IN/8];    // half copy of input_kv
__device__ uint4 g_Xq4 [(size_t)MQ*CH_LAT/8];    // half copy of latent
__device__ uint4 g_Qb4 [(size_t)BH*LQ*DH/8];     // half [bh][q][d], QSCALE folded
__device__ uint4 g_Kb4 [(size_t)BH*LKV*DH/8];    // half [bh][l][d]
__device__ uint4 g_Vt4 [(size_t)BH*DH*LKV/8];    // half [bh][d][l]
__device__ uint4 g_AO4 [(size_t)MQ*1024/8];      // half [b*512+q][h*128+d]
__device__ uint4 g_WTkv4[2048*768/8];            // half (gamma*W)^T; <1024: K, >=1024: V
__device__ uint4 g_WTq4 [1024*1024/8];
__device__ uint4 g_WTo4 [1024*1024/8];
__device__ float g_vb[2048], g_vg[2048];         // beta^T W, gamma^T W (KV)
__device__ float g_vbq[1024], g_vgq[1024];       // (Q)
__device__ float g_vbp[8*2048], g_vgp[8*2048];   // split-K partials
__device__ unsigned g_vcnt = 0;                  // completion ticket (self-resetting)

// ---------------------------------------------------------------------------
// helpers
// ---------------------------------------------------------------------------
__device__ __forceinline__ float ex2(float x) {
    float y; asm("ex2.approx.ftz.f32 %0, %1;" : "=f"(y) : "f"(x)); return y;
}
__device__ __forceinline__ unsigned pack2h(float a, float b) {
    __half2 h = __floats2half2_rn(a, b);
    return *(unsigned*)&h;
}
__device__ __forceinline__ uint32_t smem_u32(const void* p) {
    uint32_t a;
    asm("{ .reg .u64 t; cvta.to.shared.u64 t, %1; cvt.u32.u64 %0, t; }" : "=r"(a) : "l"(p));
    return a;
}
__device__ __forceinline__ void cpa16(uint32_t dst, const void* src) {
    asm volatile("cp.async.cg.shared.global [%0], [%1], 16;" :: "r"(dst), "l"(src));
}
#define CP_COMMIT() asm volatile("cp.async.commit_group;")
#define CP_WAIT(N)  asm volatile("cp.async.wait_group %0;" :: "n"(N))

__device__ __forceinline__ void mma_f16(float* c, const unsigned* a, const unsigned* b) {
    asm volatile(
        "mma.sync.aligned.m16n8k16.row.col.f32.f16.f16.f32 "
        "{%0,%1,%2,%3}, {%4,%5,%6,%7}, {%8,%9}, {%0,%1,%2,%3};\n"
        : "+f"(c[0]), "+f"(c[1]), "+f"(c[2]), "+f"(c[3])
        : "r"(a[0]), "r"(a[1]), "r"(a[2]), "r"(a[3]), "r"(b[0]), "r"(b[1]));
}
__device__ __forceinline__ void ldsm4(unsigned* r, uint32_t a) {
    asm volatile("ldmatrix.sync.aligned.m8n8.x4.shared.b16 {%0,%1,%2,%3}, [%4];"
                 : "=r"(r[0]), "=r"(r[1]), "=r"(r[2]), "=r"(r[3]) : "r"(a));
}

// ---------------------------------------------------------------------------
// Row stats + half copy (one warp per row)
// ---------------------------------------------------------------------------
__global__ void rowstats_kernel(const float* __restrict__ X, __half* __restrict__ Xh,
                                float* __restrict__ mu, float* __restrict__ rs, int cols)
{
    int row  = blockIdx.x * 8 + (threadIdx.x >> 5);
    int lane = threadIdx.x & 31;
    const float* xr = X + (size_t)row * cols;
    __half* xo = Xh + (size_t)row * cols;
    float s = 0.f, s2 = 0.f;
    for (int c = lane; c < cols; c += 32) {
        float v = xr[c];
        xo[c] = __float2half_rn(v);
        s += v; s2 += v * v;
    }
#pragma unroll
    for (int o = 16; o; o >>= 1) {
        s  += __shfl_xor_sync(0xffffffffu, s,  o);
        s2 += __shfl_xor_sync(0xffffffffu, s2, o);
    }
    if (lane == 0) {
        float m = s / cols;
        float var = fmaxf(s2 / cols - m * m, 0.f);
        mu[row] = m; rs[row] = rsqrtf(var + 1e-5f);
    }
}

// ---------------------------------------------------------------------------
// Weight transpose: out[c][r] = half(in[r][c] * (scale?scale[r]:1))
// Single-matrix and z-merged two-matrix variants.
// ---------------------------------------------------------------------------
__global__ void wtrans_kernel(const float* __restrict__ in, __half* __restrict__ out,
                              int R, int C, const float* __restrict__ scale)
{
    __shared__ float t[32][33];
    int c0 = blockIdx.x * 32, r0 = blockIdx.y * 32;
    int tx = threadIdx.x, ty = threadIdx.y;
#pragma unroll
    for (int j = 0; j < 4; j++) {
        int r = r0 + ty + j * 8;
        float v = in[(size_t)r * C + c0 + tx];
        if (scale) v *= scale[r];
        t[ty + j * 8][tx] = v;
    }
    __syncthreads();
#pragma unroll
    for (int j = 0; j < 4; j++)
        out[(size_t)(c0 + ty + j * 8) * R + r0 + tx] = __float2half_rn(t[tx][ty + j * 8]);
}

__global__ void wtrans2_kernel(const float* __restrict__ inA, const float* __restrict__ inB,
                               __half* __restrict__ out, int R, int C,
                               const float* __restrict__ scale)
{
    __shared__ float t[32][33];
    const float* in = blockIdx.z ? inB : inA;
    __half* o = out + (size_t)blockIdx.z * C * R;
    int c0 = blockIdx.x * 32, r0 = blockIdx.y * 32;
    int tx = threadIdx.x, ty = threadIdx.y;
#pragma unroll
    for (int j = 0; j < 4; j++) {
        int r = r0 + ty + j * 8;
        float v = in[(size_t)r * C + c0 + tx] * scale[r];
        t[ty + j * 8][tx] = v;
    }
    __syncthreads();
#pragma unroll
    for (int j = 0; j < 4; j++)
        o[(size_t)(c0 + ty + j * 8) * R + r0 + tx] = __float2half_rn(t[tx][ty + j * 8]);
}

// ---------------------------------------------------------------------------
// vb/vg fold vectors: split-K partials, last block reduces (ticket counter).
// ---------------------------------------------------------------------------
__global__ void vbvg_fused(const float* __restrict__ W0, const float* __restrict__ W1,
                           const float* __restrict__ gamma, const float* __restrict__ beta,
                           float* __restrict__ vbp, float* __restrict__ vgp,
                           float* __restrict__ vb, float* __restrict__ vg,
                           int N, int rows_per_slice)
{
    __shared__ float sbv[4][64], sgv[4][64];
    __shared__ unsigned ticket;
    int nl = threadIdx.x & 63;
    int n = blockIdx.x * 64 + nl;
    int rg = threadIdx.x >> 6;
    int r0 = blockIdx.y * rows_per_slice;
    const float* W = (n < 1024) ? W0 : W1;
    int nn = n & 1023;
    float sb = 0.f, sg = 0.f;
#pragma unroll 4
    for (int r = r0 + rg; r < r0 + rows_per_slice; r += 4) {
        float w = W[(size_t)r * 1024 + nn];
        sb += beta[r] * w;
        sg += gamma[r] * w;
    }
    sbv[rg][nl] = sb;
    sgv[rg][nl] = sg;
    __syncthreads();
    if (threadIdx.x < 64) {
        vbp[(size_t)blockIdx.y * N + n] = sbv[0][nl] + sbv[1][nl] + sbv[2][nl] + sbv[3][nl];
        vgp[(size_t)blockIdx.y * N + n] = sgv[0][nl] + sgv[1][nl] + sgv[2][nl] + sgv[3][nl];
    }
    __threadfence();
    __syncthreads();
    if (threadIdx.x == 0) ticket = atomicAdd(&g_vcnt, 1u);
    __syncthreads();
    if (ticket == gridDim.x * gridDim.y - 1) {
        int S = gridDim.y;
        for (int nn2 = (int)threadIdx.x; nn2 < N; nn2 += 256) {
            float a = 0.f, b = 0.f;
            for (int s = 0; s < S; s++) {
                a += vbp[(size_t)s * N + nn2];
                b += vgp[(size_t)s * N + nn2];
            }
            vb[nn2] = a; vg[nn2] = b;
        }
        __threadfence();
        if (threadIdx.x == 0) g_vcnt = 0;
    }
}

// ---------------------------------------------------------------------------
// FP16 GEMM (R14-proven): block 128x256, BK=64, 256 threads, warp 64x64,
// m16n8k16, cp.async 3-stage, ldmatrix loads. blk' = blk ^ (row&7).
// ---------------------------------------------------------------------------
#define G_STAGE 49152
#define G_SMEM  (3*G_STAGE)      // 144KB

template<int MODE>
__global__ __launch_bounds__(256, 1)
void gemm_h(const __half* __restrict__ A, const __half* __restrict__ WT,
            const float* __restrict__ mu, const float* __restrict__ rs,
            const float* __restrict__ vb, const float* __restrict__ vg,
            float* __restrict__ C, int K)
{
    extern __shared__ char sm[];
    const uint32_t sb = smem_u32(sm);
    const int tid = threadIdx.x;
    const int lane = tid & 31, wid = tid >> 5;
    const int wm = wid >> 2, wn = wid & 3;
    const int g = lane >> 2, t = lane & 3;
    const int m0 = blockIdx.y * 128, n0 = blockIdx.x * 256;
    const int KC = K >> 6;

    const int srow = tid >> 3, sblk = tid & 7;
    const __half* a_src0 = A  + (size_t)(m0 + srow) * K + sblk * 8;
    const __half* b_src0 = WT + (size_t)(n0 + srow) * K + sblk * 8;
    const uint32_t s_dst0 = (uint32_t)(srow * 128 + (((sblk ^ (srow & 7)) & 7) << 4));

    const int a_row = ((lane >> 3) & 1) * 8 + (lane & 7);
    const int a_ch  = lane >> 4;
    const int ax7   = a_row & 7;
    const uint32_t a_ro = (uint32_t)(wm * 64 + a_row) * 128;
    const int b_row = ((lane >> 4) & 1) * 8 + (lane & 7);
    const int b_ch  = (lane >> 3) & 1;
    const int bx7   = b_row & 7;
    const uint32_t b_ro = 16384u + (uint32_t)(wn * 64 + b_row) * 128;

    float acc[4][8][4];
#pragma unroll
    for (int i = 0; i < 4; i++)
#pragma unroll
        for (int j = 0; j < 8; j++)
#pragma unroll
            for (int r = 0; r < 4; r++) acc[i][j][r] = 0.f;

#pragma unroll
    for (int s = 0; s < 2; s++) {
        uint32_t base = sb + s * G_STAGE;
        int k0 = s * 64;
#pragma unroll
        for (int it = 0; it < 4; it++)
            cpa16(base + s_dst0 + it * 4096, a_src0 + (size_t)it * 32 * K + k0);
#pragma unroll
        for (int it = 0; it < 8; it++)
            cpa16(base + 16384 + s_dst0 + it * 4096, b_src0 + (size_t)it * 32 * K + k0);
        CP_COMMIT();
    }

    for (int c = 0; c < KC; c++) {
        CP_WAIT(1);
        __syncthreads();
        if (c + 2 < KC) {
            uint32_t base = sb + ((c + 2) % 3) * G_STAGE;
            int k0 = (c + 2) * 64;
#pragma unroll
            for (int it = 0; it < 4; it++)
                cpa16(base + s_dst0 + it * 4096, a_src0 + (size_t)it * 32 * K + k0);
#pragma unroll
            for (int it = 0; it < 8; it++)
                cpa16(base + 16384 + s_dst0 + it * 4096, b_src0 + (size_t)it * 32 * K + k0);
        }
        CP_COMMIT();

        const uint32_t abase = sb + (c % 3) * G_STAGE;
#pragma unroll
        for (int ks = 0; ks < 4; ks++) {
            unsigned afr[4][4], bfr[8][2];
            uint32_t aoff = abase + a_ro + ((((ks * 2 + a_ch) ^ ax7) & 7) << 4);
#pragma unroll
            for (int i = 0; i < 4; i++) ldsm4(afr[i], aoff + i * 2048);
            uint32_t boff = abase + b_ro + ((((ks * 2 + b_ch) ^ bx7) & 7) << 4);
#pragma unroll
            for (int jp = 0; jp < 4; jp++) {
                unsigned tmp[4];
                ldsm4(tmp, boff + jp * 2048);
                bfr[2*jp][0] = tmp[0]; bfr[2*jp][1] = tmp[1];
                bfr[2*jp+1][0] = tmp[2]; bfr[2*jp+1][1] = tmp[3];
            }
#pragma unroll
            for (int i = 0; i < 4; i++)
#pragma unroll
                for (int j = 0; j < 8; j++)
                    mma_f16(acc[i][j], afr[i], bfr[j]);
        }
    }
    CP_WAIT(0);
    __syncthreads();

    // ---- epilogue
    float Rr[8], MR[8];
    if (MODE != 2) {
#pragma unroll
        for (int i = 0; i < 4; i++)
#pragma unroll
            for (int half = 0; half < 2; half++) {
                int r = m0 + wm * 64 + i * 16 + g + half * 8;
                float rv = rs[r];
                Rr[i * 2 + half] = rv;
                MR[i * 2 + half] = mu[r] * rv;
            }
    }
    float vbv[16], vgv[16];
    if (MODE != 2) {
#pragma unroll
        for (int j = 0; j < 8; j++) {
            int cg = n0 + wn * 64 + j * 8 + 2 * t;
            vbv[2*j] = vb[cg]; vbv[2*j+1] = vb[cg+1];
            vgv[2*j] = vg[cg]; vgv[2*j+1] = vg[cg+1];
        }
    }

    const bool vpart = (MODE == 0) && (n0 >= 1024);
    __half* st = (__half*)sm;
    __half* Kb = (__half*)g_Kb4;
    __half* Qb = (__half*)g_Qb4;
    __half* Vt = (__half*)g_Vt4;

#pragma unroll
    for (int i = 0; i < 4; i++) {
#pragma unroll
        for (int j = 0; j < 8; j++) {
#pragma unroll
            for (int half = 0; half < 2; half++) {
                int rl = wm * 64 + i * 16 + g + half * 8;
                int r = m0 + rl;
                int cl = wn * 64 + j * 8 + 2 * t;
                int cg = n0 + cl;
                float v0 = acc[i][j][half * 2 + 0];
                float v1 = acc[i][j][half * 2 + 1];
                if (MODE != 2) {
                    float R = Rr[i * 2 + half], M = MR[i * 2 + half];
                    v0 = R * v0 + vbv[2*j]   - M * vgv[2*j];
                    v1 = R * v1 + vbv[2*j+1] - M * vgv[2*j+1];
                }
                if (MODE == 0) {
                    if (!vpart) {
                        int h = cg >> 7, d = cg & 127;
                        int bb2 = r >> 14, l = r & 16383;
                        unsigned u = pack2h(v0, v1);
                        *(unsigned*)(Kb + ((((size_t)(bb2 * 8 + h)) << 14) + l) * 128 + d) = u;
                    } else {
                        st[cl * 136 + rl]       = __float2half_rn(v0);
                        st[(cl + 1) * 136 + rl] = __float2half_rn(v1);
                    }
                } else if (MODE == 1) {
                    int h = cg >> 7, d = cg & 127;
                    int bb2 = r >> 9, q = r & 511;
                    unsigned u = pack2h(QSCALE * v0, QSCALE * v1);
                    *(unsigned*)(Qb + (((size_t)(bb2 * 8 + h)) * 512 + q) * 128 + d) = u;
                } else {
                    *(float2*)(C + (size_t)r * 1024 + cg) = make_float2(v0, v1);
                }
            }
        }
    }
    if (vpart) {
        __syncthreads();
        int bb2 = m0 >> 14, l0 = m0 & 16383;
#pragma unroll
        for (int cl2 = 0; cl2 < 32; cl2++) {
            int c = wid * 32 + cl2;
            int cg = n0 + c - 1024;
            int h = cg >> 7, d = cg & 127;
            uint2 v = *(const uint2*)&st[c * 136 + lane * 4];
            *(uint2*)(Vt + ((size_t)(bb2 * 8 + h) * 128 + d) * LKV + l0 + lane * 4) = v;
        }
    }
}

// ---------------------------------------------------------------------------
// FP16 flash attention, register-resident P (FA2-style).
// Br=128, Bc=128, 256 threads. Warp w owns q rows w*16..w*16+15 x all 128 l.
// S C-fragments are re-packed in registers as the PV A-fragments (layout
// identity of m16n8k16). No P smem, no mid-chunk sync, no cross-warp rowsum.
// cp.async 3-stage K/V prefetch. Smem: Q 32KB | 3 x (K32+V32) = 224KB.
// ---------------------------------------------------------------------------
#define AT_Q     0
#define AT_STG   32768
#define A_SMEM_BYTES (32768 + 3*65536)   // 229376

__global__ __launch_bounds__(256, 1)
void attn_h(const __half* __restrict__ Qb, const __half* __restrict__ Kb,
            const __half* __restrict__ Vt, __half* __restrict__ AO)
{
    extern __shared__ char sm[];
    const uint32_t sb = smem_u32(sm);
    const int tid = threadIdx.x;
    const int lane = tid & 31, wid = tid >> 5;
    const int g = lane >> 2, t = lane & 3;
    const int bh = blockIdx.y;
    const int q0 = blockIdx.x * 128;

    const __half* Qg = Qb + ((size_t)bh * LQ + q0) * DH;
    const __half* Kg = Kb + (size_t)bh * LKV * DH;
    const __half* Vg = Vt + (size_t)bh * DH * LKV;

    // ldmatrix per-lane geometry
    const int ar = ((lane >> 3) & 1) * 8 + (lane & 7);    // A-op rows 0..15
    const int ach = lane >> 4;
    const int br = ((lane >> 4) & 1) * 8 + (lane & 7);    // B-op rows 0..15
    const int bch = (lane >> 3) & 1;
    const uint32_t q_ro = sb + AT_Q + (uint32_t)(wid * 16 + ar) * 256;

    // staging assignments (K rows l 0..127, V rows d 0..127; 16 x16B each)
    const __half* k_src[8]; uint32_t k_dst[8];
    const __half* v_src[8]; uint32_t v_dst[8];
#pragma unroll
    for (int it = 0; it < 8; it++) {
        int idx = tid + it * 256, row = idx >> 4, blk = idx & 15;
        uint32_t sw = (row * 64 + (((blk ^ row) & 15) << 2)) * 4;
        k_src[it] = Kg + (size_t)row * 128 + blk * 8;
        k_dst[it] = sw;
        v_src[it] = Vg + (size_t)row * LKV + blk * 8;
        v_dst[it] = 32768 + sw;
    }

    // prologue: Q + chunks 0,1,2 (groups 0,1,2)
#pragma unroll
    for (int it = 0; it < 8; it++) {
        int idx = tid + it * 256, row = idx >> 4, blk = idx & 15;
        cpa16(sb + AT_Q + (row * 64 + (((blk ^ row) & 15) << 2)) * 4,
              Qg + (size_t)row * 128 + blk * 8);
    }
#pragma unroll
    for (int s = 0; s < 3; s++) {
        uint32_t base = sb + AT_STG + s * 65536;
        size_t koff = (size_t)s * 128 * 128;
        int voff = s * 128;
#pragma unroll
        for (int it = 0; it < 8; it++) cpa16(base + k_dst[it], k_src[it] + koff);
#pragma unroll
        for (int it = 0; it < 8; it++) cpa16(base + v_dst[it], v_src[it] + voff);
        CP_COMMIT();
    }

    float oacc[16][4];
#pragma unroll
    for (int nt = 0; nt < 16; nt++)
#pragma unroll
        for (int r = 0; r < 4; r++) oacc[nt][r] = 0.f;
    float rsum0 = 0.f, rsum1 = 0.f;

    const int NC = LKV / 128;
    for (int ci = 0; ci < NC; ci++) {
        CP_WAIT(2);
        __syncthreads();
        const uint32_t stg = sb + AT_STG + (ci % 3) * 65536;
        const uint32_t k_ro = stg + (uint32_t)br * 256;
        const uint32_t v_ro = stg + 32768 + (uint32_t)br * 256;

        // ---- S = Q K^T : warp 16q x 128l (16 n-tiles, 8 k-steps)
        float sac[16][4];
#pragma unroll
        for (int j = 0; j < 16; j++)
#pragma unroll
            for (int r = 0; r < 4; r++) sac[j][r] = 0.f;
#pragma unroll
        for (int ks = 0; ks < 8; ks++) {
            unsigned afr[4], bfr[16][2];
            uint32_t qa = q_ro + ((((ks * 2 + ach) ^ ar) & 15) << 4);
            ldsm4(afr, qa);
            uint32_t ka = k_ro + ((((ks * 2 + bch) ^ br) & 15) << 4);
#pragma unroll
            for (int jp = 0; jp < 8; jp++) {
                unsigned tmp[4];
                ldsm4(tmp, ka + jp * 4096);
                bfr[2*jp][0] = tmp[0]; bfr[2*jp][1] = tmp[1];
                bfr[2*jp+1][0] = tmp[2]; bfr[2*jp+1][1] = tmp[3];
            }
#pragma unroll
            for (int j = 0; j < 16; j++)
                mma_f16(sac[j], afr, bfr[j]);
        }

        // ---- P = exp2(S) in registers; re-pack C-frag -> A-frag; row sums
        unsigned pp[8][4];
#pragma unroll
        for (int kt = 0; kt < 8; kt++) {
            float e00 = ex2(sac[2*kt][0]),   e01 = ex2(sac[2*kt][1]);
            float e02 = ex2(sac[2*kt][2]),   e03 = ex2(sac[2*kt][3]);
            float e10 = ex2(sac[2*kt+1][0]), e11 = ex2(sac[2*kt+1][1]);
            float e12 = ex2(sac[2*kt+1][2]), e13 = ex2(sac[2*kt+1][3]);
            rsum0 += e00 + e01 + e10 + e11;
            rsum1 += e02 + e03 + e12 + e13;
            pp[kt][0] = pack2h(e00, e01);
            pp[kt][1] = pack2h(e02, e03);
            pp[kt][2] = pack2h(e10, e11);
            pp[kt][3] = pack2h(e12, e13);
        }

        // ---- O += P V : warp 16q x 128d (16 n-tiles, 8 k-tiles)
#pragma unroll
        for (int kt = 0; kt < 8; kt++) {
            unsigned bfr[16][2];
            uint32_t va = v_ro + ((((kt * 2 + bch) ^ br) & 15) << 4);
#pragma unroll
            for (int jp = 0; jp < 8; jp++) {
                unsigned tmp[4];
                ldsm4(tmp, va + jp * 4096);
                bfr[2*jp][0] = tmp[0]; bfr[2*jp][1] = tmp[1];
                bfr[2*jp+1][0] = tmp[2]; bfr[2*jp+1][1] = tmp[3];
            }
#pragma unroll
            for (int nt = 0; nt < 16; nt++)
                mma_f16(oacc[nt], pp[kt], bfr[nt]);
        }
        __syncthreads();   // all warps done reading stage (ci%3) before refill

        if (ci + 3 < NC) {
            uint32_t base = sb + AT_STG + (ci % 3) * 65536;
            size_t koff = (size_t)(ci + 3) * 128 * 128;
            int voff = (ci + 3) * 128;
#pragma unroll
            for (int it = 0; it < 8; it++) cpa16(base + k_dst[it], k_src[it] + koff);
#pragma unroll
            for (int it = 0; it < 8; it++) cpa16(base + v_dst[it], v_src[it] + voff);
        }
        CP_COMMIT();
    }

    // ---- row sums: reduce over quad lanes (t) only; warp owns its rows
    rsum0 += __shfl_xor_sync(0xffffffffu, rsum0, 1);
    rsum0 += __shfl_xor_sync(0xffffffffu, rsum0, 2);
    rsum1 += __shfl_xor_sync(0xffffffffu, rsum1, 1);
    rsum1 += __shfl_xor_sync(0xffffffffu, rsum1, 2);
    float inv0 = 1.f / rsum0, inv1 = 1.f / rsum1;

    // ---- epilogue: normalize, scatter (half2)
    int bb2 = bh >> 3, h = bh & 7;
    size_t row0 = ((size_t)(bb2 * 512 + q0 + wid * 16 + g)) * 1024 + h * 128;
    size_t row1 = row0 + (size_t)8 * 1024;
#pragma unroll
    for (int nt = 0; nt < 16; nt++) {
        int cc = nt * 8 + 2 * t;
        *(unsigned*)(AO + row0 + cc) = pack2h(oacc[nt][0] * inv0, oacc[nt][1] * inv0);
        *(unsigned*)(AO + row1 + cc) = pack2h(oacc[nt][2] * inv1, oacc[nt][3] * inv1);
    }
}

// ---------------------------------------------------------------------------
// Launcher. gemm_h<0> is OUR launch index 3 (harness prepends 2 -> ncu -s 5).
// ---------------------------------------------------------------------------
extern "C" void kernel_launch(void* const* d_in, const int* in_sizes, int n_in,
                              void* d_out, int out_size)
{
    (void)in_sizes; (void)n_in; (void)out_size;
    const float* latent   = (const float*)d_in[0];
    const float* inpkv    = (const float*)d_in[1];
    const float* W_Q      = (const float*)d_in[2];
    const float* W_K      = (const float*)d_in[3];
    const float* W_V      = (const float*)d_in[4];
    const float* W_O      = (const float*)d_in[5];
    const float* ln_lat_g = (const float*)d_in[6];
    const float* ln_lat_b = (const float*)d_in[7];
    const float* ln_in_g  = (const float*)d_in[8];
    const float* ln_in_b  = (const float*)d_in[9];
    float* out = (float*)d_out;

    float *p_mukv, *p_rskv, *p_muq, *p_rsq, *p_vb, *p_vg, *p_vbq, *p_vgq, *p_vbp, *p_vgp;
    void *p_Xkv, *p_Xq, *p_Q, *p_K, *p_Vt, *p_AO, *p_WTkv, *p_WTq, *p_WTo;
    cudaGetSymbolAddress((void**)&p_mukv, g_mu_kv);
    cudaGetSymbolAddress((void**)&p_rskv, g_rs_kv);
    cudaGetSymbolAddress((void**)&p_muq,  g_mu_q);
    cudaGetSymbolAddress((void**)&p_rsq,  g_rs_q);
    cudaGetSymbolAddress(&p_Xkv,  g_Xkv4);
    cudaGetSymbolAddress(&p_Xq,   g_Xq4);
    cudaGetSymbolAddress(&p_Q,    g_Qb4);
    cudaGetSymbolAddress(&p_K,    g_Kb4);
    cudaGetSymbolAddress(&p_Vt,   g_Vt4);
    cudaGetSymbolAddress(&p_AO,   g_AO4);
    cudaGetSymbolAddress(&p_WTkv, g_WTkv4);
    cudaGetSymbolAddress(&p_WTq,  g_WTq4);
    cudaGetSymbolAddress(&p_WTo,  g_WTo4);
    cudaGetSymbolAddress((void**)&p_vb,  g_vb);
    cudaGetSymbolAddress((void**)&p_vg,  g_vg);
    cudaGetSymbolAddress((void**)&p_vbq, g_vbq);
    cudaGetSymbolAddress((void**)&p_vgq, g_vgq);
    cudaGetSymbolAddress((void**)&p_vbp, g_vbp);
    cudaGetSymbolAddress((void**)&p_vgp, g_vgp);

    cudaFuncSetAttribute(gemm_h<0>, cudaFuncAttributeMaxDynamicSharedMemorySize, G_SMEM);
    cudaFuncSetAttribute(gemm_h<1>, cudaFuncAttributeMaxDynamicSharedMemorySize, G_SMEM);
    cudaFuncSetAttribute(gemm_h<2>, cudaFuncAttributeMaxDynamicSharedMemorySize, G_SMEM);
    cudaFuncSetAttribute(attn_h,    cudaFuncAttributeMaxDynamicSharedMemorySize, A_SMEM_BYTES);

    dim3 tb(32, 8);
    // 0: KV row stats + half copy
    rowstats_kernel<<<MKV / 8, 256>>>(inpkv, (__half*)p_Xkv, p_mukv, p_rskv, CH_IN);
    // 1: K|V weight transposes (z-merged, gamma folded)
    wtrans2_kernel<<<dim3(32, 24, 2), tb>>>(W_K, W_V, (__half*)p_WTkv, 768, 1024, ln_in_g);
    // 2: LN fold vectors for K|V (fused split-K)
    vbvg_fused<<<dim3(32, 6), 256>>>(W_K, W_V, ln_in_g, ln_in_b,
                                     p_vbp, p_vgp, p_vb, p_vg, 2048, 128);
    // 3: K|V projection  <-- profiled (ncu -s 5)
    gemm_h<0><<<dim3(8, 1024), 256, G_SMEM>>>((const __half*)p_Xkv, (const __half*)p_WTkv,
                                              p_mukv, p_rskv, p_vb, p_vg, nullptr, CH_IN);
    // 4: Q row stats + half copy
    rowstats_kernel<<<MQ / 8, 256>>>(latent, (__half*)p_Xq, p_muq, p_rsq, CH_LAT);
    // 5,6: Q weight prep
    wtrans_kernel<<<dim3(32, 32), tb>>>(W_Q, (__half*)p_WTq, 1024, 1024, ln_lat_g);
    vbvg_fused<<<dim3(16, 8), 256>>>(W_Q, W_Q, ln_lat_g, ln_lat_b,
                                     p_vbp, p_vgp, p_vbq, p_vgq, 1024, 128);
    // 7: Q projection
    gemm_h<1><<<dim3(4, 32), 256, G_SMEM>>>((const __half*)p_Xq, (const __half*)p_WTq,
                                            p_muq, p_rsq, p_vbq, p_vgq, nullptr, CH_LAT);
    // 8: flash attention (register-P)
    attn_h<<<dim3(4, BH), 256, A_SMEM_BYTES>>>((const __half*)p_Q, (const __half*)p_K,
                                               (const __half*)p_Vt, (__half*)p_AO);
    // 9: O weight transpose
    wtrans_kernel<<<dim3(32, 32), tb>>>(W_O, (__half*)p_WTo, 1024, 1024, nullptr);
    // 10: output projection (float out)
    gemm_h<2><<<dim3(4, 32), 256, G_SMEM>>>((const __half*)p_AO, (const __half*)p_WTo,
                                            nullptr, nullptr, nullptr, nullptr, out, 1024);
}